// round 1
// baseline (speedup 1.0000x reference)
#include <cuda_runtime.h>

#define N_TOK 1024
#define LDIM  256
#define HDIM  512
#define H2DIM 256

// scratch (allocation-free rule: __device__ globals)
__device__ float g_ah[N_TOK * HDIM];
__device__ float g_am[N_TOK * HDIM];
__device__ float g_At[H2DIM * N_TOK];   // A + hid2Bias, transposed [h2][i]
__device__ float g_Bt[H2DIM * N_TOK];   // B, transposed [h2][j]

__device__ __forceinline__ float tanh_apx(float x) {
    float y;
    asm("tanh.approx.f32 %0, %1;" : "=f"(y) : "f"(x));
    return y;
}

// ---------------------------------------------------------------------------
// P1: ah/am[i][h] = tanh( concat(l0,l1)[i,:] @ W[:,h] + catBias[z*H + h] )
// M=1024 (tokens), N=512 (h), K=512. 64x64 tiles, BK=16, 4x4 micro.
// z=0 -> W_foh/g_ah, z=1 -> W_fom/g_am
// ---------------------------------------------------------------------------
__global__ __launch_bounds__(256) void p1_kernel(
    const float* __restrict__ l0, const float* __restrict__ l1,
    const float* __restrict__ Wfoh, const float* __restrict__ Wfom,
    const float* __restrict__ catBias)
{
    const int z = blockIdx.z;
    const float* __restrict__ W = z ? Wfom : Wfoh;
    float* __restrict__ out = z ? g_am : g_ah;
    const int m0 = blockIdx.x * 64;
    const int n0 = blockIdx.y * 64;
    const int tid = threadIdx.x;
    const int tx = tid & 15, ty = tid >> 4;

    __shared__ float Xs[64][17];
    __shared__ float Ws[16][64];

    float acc[4][4] = {};

    for (int k0 = 0; k0 < 2 * LDIM; k0 += 16) {
        // X tile: rows m0..m0+63, k k0..k0+15 (never straddles the l0/l1 seam)
        const float* __restrict__ src = (k0 < LDIM) ? (l0 + k0) : (l1 + (k0 - LDIM));
        #pragma unroll
        for (int q = 0; q < 4; q++) {
            int e = q * 256 + tid;
            int m = e >> 4, k = e & 15;
            Xs[m][k] = src[(m0 + m) * LDIM + k];
        }
        // W tile: rows k0..k0+15, cols n0..n0+63
        #pragma unroll
        for (int q = 0; q < 4; q++) {
            int e = q * 256 + tid;
            int r = e >> 6, c = e & 63;
            Ws[r][c] = W[(k0 + r) * HDIM + n0 + c];
        }
        __syncthreads();

        #pragma unroll
        for (int kk = 0; kk < 16; kk++) {
            float a[4];
            #pragma unroll
            for (int di = 0; di < 4; di++) a[di] = Xs[ty * 4 + di][kk];
            float4 bv = *(const float4*)&Ws[kk][tx * 4];
            float b[4] = {bv.x, bv.y, bv.z, bv.w};
            #pragma unroll
            for (int di = 0; di < 4; di++)
                #pragma unroll
                for (int dj = 0; dj < 4; dj++)
                    acc[di][dj] += a[di] * b[dj];
        }
        __syncthreads();
    }

    const float* __restrict__ cb = catBias + z * HDIM + n0 + tx * 4;
    float b0 = cb[0], b1 = cb[1], b2 = cb[2], b3 = cb[3];
    #pragma unroll
    for (int di = 0; di < 4; di++) {
        int row = m0 + ty * 4 + di;
        float4 o;
        o.x = tanh_apx(acc[di][0] + b0);
        o.y = tanh_apx(acc[di][1] + b1);
        o.z = tanh_apx(acc[di][2] + b2);
        o.w = tanh_apx(acc[di][3] + b3);
        *(float4*)&out[row * HDIM + n0 + tx * 4] = o;
    }
}

// ---------------------------------------------------------------------------
// P2: At[h2][i] = ah[i,:] @ hid2[0:H, h2] + hid2Bias[h2]   (z=0)
//     Bt[h2][j] = am[j,:] @ hid2[H:2H, h2]                 (z=1)
// M=1024, N=256 (h2), K=512. Output stored TRANSPOSED (scattered stores are
// negligible: 0.5M floats per z).
// ---------------------------------------------------------------------------
__global__ __launch_bounds__(256) void p2_kernel(
    const float* __restrict__ hid2, const float* __restrict__ hid2Bias)
{
    const int z = blockIdx.z;
    const float* __restrict__ src = z ? g_am : g_ah;
    float* __restrict__ out = z ? g_Bt : g_At;
    const int m0 = blockIdx.x * 64;
    const int n0 = blockIdx.y * 64;
    const int tid = threadIdx.x;
    const int tx = tid & 15, ty = tid >> 4;

    __shared__ float Xs[64][17];
    __shared__ float Ws[16][64];

    float acc[4][4] = {};

    for (int k0 = 0; k0 < HDIM; k0 += 16) {
        #pragma unroll
        for (int q = 0; q < 4; q++) {
            int e = q * 256 + tid;
            int m = e >> 4, k = e & 15;
            Xs[m][k] = src[(m0 + m) * HDIM + k0 + k];
        }
        #pragma unroll
        for (int q = 0; q < 4; q++) {
            int e = q * 256 + tid;
            int r = e >> 6, c = e & 63;
            Ws[r][c] = hid2[(z * HDIM + k0 + r) * H2DIM + n0 + c];
        }
        __syncthreads();

        #pragma unroll
        for (int kk = 0; kk < 16; kk++) {
            float a[4];
            #pragma unroll
            for (int di = 0; di < 4; di++) a[di] = Xs[ty * 4 + di][kk];
            float4 bv = *(const float4*)&Ws[kk][tx * 4];
            float b[4] = {bv.x, bv.y, bv.z, bv.w};
            #pragma unroll
            for (int di = 0; di < 4; di++)
                #pragma unroll
                for (int dj = 0; dj < 4; dj++)
                    acc[di][dj] += a[di] * b[dj];
        }
        __syncthreads();
    }

    float bias[4] = {0.f, 0.f, 0.f, 0.f};
    if (z == 0) {
        #pragma unroll
        for (int dj = 0; dj < 4; dj++) bias[dj] = hid2Bias[n0 + tx * 4 + dj];
    }
    #pragma unroll
    for (int dj = 0; dj < 4; dj++) {
        int h2 = n0 + tx * 4 + dj;
        #pragma unroll
        for (int di = 0; di < 4; di++) {
            int i = m0 + ty * 4 + di;
            out[h2 * N_TOK + i] = acc[di][dj] + bias[dj];
        }
    }
}

// ---------------------------------------------------------------------------
// Main pairwise kernel: scores[i][j] = outBias + sum_h tanh(At[h][i]+Bt[h][j]) * w[h]
// 64x64 CTA tile, 4x4 micro, h chunked by 64. grid 16x16 = 256 CTAs
// = one full wave at 2 CTAs/SM. MUFU(tanh)-bound by design.
// ---------------------------------------------------------------------------
__global__ __launch_bounds__(256, 2) void pair_kernel(
    const float* __restrict__ outLayer, const float* __restrict__ outBias,
    float* __restrict__ out)
{
    const int j0 = blockIdx.x * 64;
    const int i0 = blockIdx.y * 64;
    const int tid = threadIdx.x;
    const int tx = tid & 15, ty = tid >> 4;

    __shared__ float sA[64][64];
    __shared__ float sB[64][64];
    __shared__ float sw[H2DIM];

    sw[tid] = outLayer[tid];
    // tid covers 0..255 == H2DIM

    float acc[4][4] = {};

    for (int h0 = 0; h0 < H2DIM; h0 += 64) {
        #pragma unroll
        for (int q = 0; q < 4; q++) {
            int e = q * 256 + tid;          // float4 units, 1024 total
            int r = e >> 4, c4 = e & 15;
            *(float4*)&sA[r][c4 * 4] =
                *(const float4*)&g_At[(h0 + r) * N_TOK + i0 + c4 * 4];
            *(float4*)&sB[r][c4 * 4] =
                *(const float4*)&g_Bt[(h0 + r) * N_TOK + j0 + c4 * 4];
        }
        __syncthreads();

        #pragma unroll 8
        for (int hk = 0; hk < 64; hk++) {
            float4 av = *(const float4*)&sA[hk][ty * 4];
            float4 bv = *(const float4*)&sB[hk][tx * 4];
            float a[4] = {av.x, av.y, av.z, av.w};
            float b[4] = {bv.x, bv.y, bv.z, bv.w};
            float wv = sw[h0 + hk];
            #pragma unroll
            for (int di = 0; di < 4; di++)
                #pragma unroll
                for (int dj = 0; dj < 4; dj++)
                    acc[di][dj] += wv * tanh_apx(a[di] + b[dj]);
        }
        __syncthreads();
    }

    const float ob = outBias[0];
    #pragma unroll
    for (int di = 0; di < 4; di++) {
        int row = i0 + ty * 4 + di;
        float4 o;
        o.x = acc[di][0] + ob;
        o.y = acc[di][1] + ob;
        o.z = acc[di][2] + ob;
        o.w = acc[di][3] + ob;
        *(float4*)&out[row * N_TOK + j0 + tx * 4] = o;
    }
}

// ---------------------------------------------------------------------------
extern "C" void kernel_launch(void* const* d_in, const int* in_sizes, int n_in,
                              void* d_out, int out_size)
{
    const float* lstms0   = (const float*)d_in[0];  // [1024, 256]
    const float* lstms1   = (const float*)d_in[1];  // [1024, 256]
    const float* W_foh    = (const float*)d_in[2];  // [512, 512]
    const float* W_fom    = (const float*)d_in[3];  // [512, 512]
    const float* catBias  = (const float*)d_in[4];  // [1, 1024]
    const float* hid2     = (const float*)d_in[5];  // [1024, 256]
    const float* hid2Bias = (const float*)d_in[6];  // [1, 256]
    const float* outLayer = (const float*)d_in[7];  // [256, 1]
    const float* outBias  = (const float*)d_in[8];  // [1, 1]
    float* out = (float*)d_out;                     // [1024, 1024]

    p1_kernel<<<dim3(N_TOK / 64, HDIM / 64, 2), 256>>>(lstms0, lstms1, W_foh, W_fom, catBias);
    p2_kernel<<<dim3(N_TOK / 64, H2DIM / 64, 2), 256>>>(hid2, hid2Bias);
    pair_kernel<<<dim3(N_TOK / 64, N_TOK / 64), 256>>>(outLayer, outBias, out);
}

// round 4
// speedup vs baseline: 1.0002x; 1.0002x over previous
#include <cuda_runtime.h>
#include <cuda_fp16.h>

#define N_TOK 1024
#define LDIM  256
#define HDIM  512
#define H2DIM 256

// scratch (allocation-free rule: __device__ globals)
__device__ float g_ah[N_TOK * HDIM];
__device__ float g_am[N_TOK * HDIM];
__device__ unsigned int g_At_rep[H2DIM * N_TOK];       // half2(A+bias, same) per [h2][i]
__device__ unsigned int g_Bt2[H2DIM * (N_TOK / 2)];    // half2(B_j, B_{j+1}) per [h2][j/2]

__device__ __forceinline__ float tanh_apx(float x) {
    float y;
    asm("tanh.approx.f32 %0, %1;" : "=f"(y) : "f"(x));
    return y;
}

__device__ __forceinline__ unsigned int tanh2_apx(unsigned int x) {
    unsigned int y;
    asm("tanh.approx.f16x2 %0, %1;" : "=r"(y) : "r"(x));
    return y;
}

// ---------------------------------------------------------------------------
// P1: ah/am[i][h] = tanh( concat(l0,l1)[i,:] @ W[:,h] + catBias[z*H + h] )
// M=1024, N=512, K=512. 128x64 tiles, BK=16, 8x4 micro. grid (8,8,2)=128 CTAs.
// ---------------------------------------------------------------------------
__global__ __launch_bounds__(256) void p1_kernel(
    const float* __restrict__ l0, const float* __restrict__ l1,
    const float* __restrict__ Wfoh, const float* __restrict__ Wfom,
    const float* __restrict__ catBias)
{
    const int z = blockIdx.z;
    const float* __restrict__ W = z ? Wfom : Wfoh;
    float* __restrict__ out = z ? g_am : g_ah;
    const int m0 = blockIdx.x * 128;
    const int n0 = blockIdx.y * 64;
    const int tid = threadIdx.x;
    const int tx = tid & 15, ty = tid >> 4;   // tx: 4 n's, ty: 8 m's

    __shared__ float Xs[16][132];   // transposed [k][m], pad for conflicts/align
    __shared__ float Ws[16][64];

    float acc[8][4] = {};

    for (int k0 = 0; k0 < 2 * LDIM; k0 += 16) {
        const float* __restrict__ src = (k0 < LDIM) ? (l0 + k0) : (l1 + (k0 - LDIM));
        #pragma unroll
        for (int q = 0; q < 8; q++) {
            int e = q * 256 + tid;
            int m = e >> 4, k = e & 15;
            Xs[k][m] = src[(m0 + m) * LDIM + k];
        }
        #pragma unroll
        for (int q = 0; q < 4; q++) {
            int e = q * 256 + tid;
            int r = e >> 6, c = e & 63;
            Ws[r][c] = W[(k0 + r) * HDIM + n0 + c];
        }
        __syncthreads();

        #pragma unroll
        for (int kk = 0; kk < 16; kk++) {
            float4 a0 = *(const float4*)&Xs[kk][ty * 8];
            float4 a1 = *(const float4*)&Xs[kk][ty * 8 + 4];
            float4 bv = *(const float4*)&Ws[kk][tx * 4];
            float a[8] = {a0.x, a0.y, a0.z, a0.w, a1.x, a1.y, a1.z, a1.w};
            float b[4] = {bv.x, bv.y, bv.z, bv.w};
            #pragma unroll
            for (int di = 0; di < 8; di++)
                #pragma unroll
                for (int dj = 0; dj < 4; dj++)
                    acc[di][dj] += a[di] * b[dj];
        }
        __syncthreads();
    }

    const float* __restrict__ cb = catBias + z * HDIM + n0 + tx * 4;
    float b0 = cb[0], b1 = cb[1], b2 = cb[2], b3 = cb[3];
    #pragma unroll
    for (int di = 0; di < 8; di++) {
        int row = m0 + ty * 8 + di;
        float4 o;
        o.x = tanh_apx(acc[di][0] + b0);
        o.y = tanh_apx(acc[di][1] + b1);
        o.z = tanh_apx(acc[di][2] + b2);
        o.w = tanh_apx(acc[di][3] + b3);
        *(float4*)&out[row * HDIM + n0 + tx * 4] = o;
    }
}

// ---------------------------------------------------------------------------
// P2: A[i][h2] = ah[i,:] @ hid2[0:H, h2] + hid2Bias[h2]  -> g_At_rep (fp16, replicated)
//     B[j][h2] = am[j,:] @ hid2[H:2H, h2]                -> g_Bt2   (fp16, j-paired)
// M=1024, N=256, K=512. 64x64 tiles, BK=16, 4x4 micro. grid (16,4,2)=128 CTAs.
// ---------------------------------------------------------------------------
__global__ __launch_bounds__(256) void p2_kernel(
    const float* __restrict__ hid2, const float* __restrict__ hid2Bias)
{
    const int z = blockIdx.z;
    const float* __restrict__ src = z ? g_am : g_ah;
    const int m0 = blockIdx.x * 64;
    const int n0 = blockIdx.y * 64;
    const int tid = threadIdx.x;
    const int tx = tid & 15, ty = tid >> 4;

    __shared__ float Xs[16][68];   // transposed [k][m]
    __shared__ float Ws[16][64];

    float acc[4][4] = {};

    for (int k0 = 0; k0 < HDIM; k0 += 16) {
        #pragma unroll
        for (int q = 0; q < 4; q++) {
            int e = q * 256 + tid;
            int m = e >> 4, k = e & 15;
            Xs[k][m] = src[(m0 + m) * HDIM + k0 + k];
        }
        #pragma unroll
        for (int q = 0; q < 4; q++) {
            int e = q * 256 + tid;
            int r = e >> 6, c = e & 63;
            Ws[r][c] = hid2[(z * HDIM + k0 + r) * H2DIM + n0 + c];
        }
        __syncthreads();

        #pragma unroll
        for (int kk = 0; kk < 16; kk++) {
            float4 av = *(const float4*)&Xs[kk][ty * 4];
            float4 bv = *(const float4*)&Ws[kk][tx * 4];
            float a[4] = {av.x, av.y, av.z, av.w};
            float b[4] = {bv.x, bv.y, bv.z, bv.w};
            #pragma unroll
            for (int di = 0; di < 4; di++)
                #pragma unroll
                for (int dj = 0; dj < 4; dj++)
                    acc[di][dj] += a[di] * b[dj];
        }
        __syncthreads();
    }

    if (z == 0) {
        // A + hid2Bias, fp16 replicated per token
        #pragma unroll
        for (int dj = 0; dj < 4; dj++) {
            int h2 = n0 + tx * 4 + dj;
            float bias = hid2Bias[h2];
            #pragma unroll
            for (int di = 0; di < 4; di++) {
                int i = m0 + ty * 4 + di;
                __half h = __float2half_rn(acc[di][dj] + bias);
                __half2 p = __half2half2(h);
                g_At_rep[h2 * N_TOK + i] = *(unsigned int*)&p;
            }
        }
    } else {
        // B, fp16 packed over adjacent tokens (j even = low half)
        #pragma unroll
        for (int dj = 0; dj < 4; dj++) {
            int h2 = n0 + tx * 4 + dj;
            #pragma unroll
            for (int dp = 0; dp < 2; dp++) {
                __half2 p = __floats2half2_rn(acc[2 * dp][dj], acc[2 * dp + 1][dj]);
                g_Bt2[h2 * (N_TOK / 2) + (m0 + ty * 4) / 2 + dp] = *(unsigned int*)&p;
            }
        }
    }
}

// ---------------------------------------------------------------------------
// Pair kernel: scores[i][j] = outBias + sum_h tanh(A[h][i]+B[h][j]) * w[h]
// fp16x2 tanh: HADD2 + tanh.f16x2 + HFMA2 per 2 elements -> MUFU-bound at 2x
// the fp32 rate. fp16 accumulators drained to fp32 every 16 h-steps.
// 64x64 CTA tile, 4x4 micro. grid 16x16 = 256 CTAs.
// ---------------------------------------------------------------------------
__global__ __launch_bounds__(256, 2) void pair_kernel(
    const float* __restrict__ outLayer, const float* __restrict__ outBias,
    float* __restrict__ out)
{
    const int j0 = blockIdx.x * 64;
    const int i0 = blockIdx.y * 64;
    const int tid = threadIdx.x;
    const int tx = tid & 15, ty = tid >> 4;  // tx: 4 j's (2 pairs), ty: 4 i's

    __shared__ unsigned int sA[64][64];  // replicated a per [hk][i]
    __shared__ unsigned int sB[64][32];  // paired b per [hk][j/2]
    __shared__ unsigned int sw2[H2DIM];  // replicated w

    {
        __half2 w = __half2half2(__float2half_rn(outLayer[tid]));
        sw2[tid] = *(unsigned int*)&w;
    }

    float facc[4][4] = {};

    for (int h0 = 0; h0 < H2DIM; h0 += 64) {
        #pragma unroll
        for (int q = 0; q < 4; q++) {
            int e = q * 256 + tid;           // uint4 units: 4096 uints total
            int r = e >> 4, c4 = e & 15;
            *(uint4*)&sA[r][c4 * 4] =
                *(const uint4*)&g_At_rep[(h0 + r) * N_TOK + i0 + c4 * 4];
        }
        #pragma unroll
        for (int q = 0; q < 2; q++) {
            int e = q * 256 + tid;           // 2048 uints
            int r = e >> 3, c2 = e & 7;
            *(uint4*)&sB[r][c2 * 4] =
                *(const uint4*)&g_Bt2[(h0 + r) * (N_TOK / 2) + j0 / 2 + c2 * 4];
        }
        __syncthreads();

        #pragma unroll
        for (int hs = 0; hs < 64; hs += 16) {
            __half2 acc2[4][2];
            #pragma unroll
            for (int di = 0; di < 4; di++)
                #pragma unroll
                for (int p = 0; p < 2; p++)
                    acc2[di][p] = __float2half2_rn(0.f);

            #pragma unroll
            for (int hh = 0; hh < 16; hh++) {
                int hk = hs + hh;
                uint4 av = *(const uint4*)&sA[hk][ty * 4];
                uint2 bv = *(const uint2*)&sB[hk][tx * 2];
                unsigned int ar[4] = {av.x, av.y, av.z, av.w};
                unsigned int br[2] = {bv.x, bv.y};
                __half2 w2 = *(__half2*)&sw2[h0 + hk];
                #pragma unroll
                for (int di = 0; di < 4; di++) {
                    #pragma unroll
                    for (int p = 0; p < 2; p++) {
                        __half2 s = __hadd2(*(__half2*)&ar[di], *(__half2*)&br[p]);
                        unsigned int t = tanh2_apx(*(unsigned int*)&s);
                        acc2[di][p] = __hfma2(w2, *(__half2*)&t, acc2[di][p]);
                    }
                }
            }
            // drain to fp32
            #pragma unroll
            for (int di = 0; di < 4; di++)
                #pragma unroll
                for (int p = 0; p < 2; p++) {
                    facc[di][2 * p]     += __low2float(acc2[di][p]);
                    facc[di][2 * p + 1] += __high2float(acc2[di][p]);
                }
        }
        __syncthreads();
    }

    const float ob = outBias[0];
    #pragma unroll
    for (int di = 0; di < 4; di++) {
        int row = i0 + ty * 4 + di;
        float4 o;
        o.x = facc[di][0] + ob;
        o.y = facc[di][1] + ob;
        o.z = facc[di][2] + ob;
        o.w = facc[di][3] + ob;
        *(float4*)&out[row * N_TOK + j0 + tx * 4] = o;
    }
}

// ---------------------------------------------------------------------------
extern "C" void kernel_launch(void* const* d_in, const int* in_sizes, int n_in,
                              void* d_out, int out_size)
{
    const float* lstms0   = (const float*)d_in[0];  // [1024, 256]
    const float* lstms1   = (const float*)d_in[1];  // [1024, 256]
    const float* W_foh    = (const float*)d_in[2];  // [512, 512]
    const float* W_fom    = (const float*)d_in[3];  // [512, 512]
    const float* catBias  = (const float*)d_in[4];  // [1, 1024]
    const float* hid2     = (const float*)d_in[5];  // [1024, 256]
    const float* hid2Bias = (const float*)d_in[6];  // [1, 256]
    const float* outLayer = (const float*)d_in[7];  // [256, 1]
    const float* outBias  = (const float*)d_in[8];  // [1, 1]
    float* out = (float*)d_out;                     // [1024, 1024]

    p1_kernel<<<dim3(N_TOK / 128, HDIM / 64, 2), 256>>>(lstms0, lstms1, W_foh, W_fom, catBias);
    p2_kernel<<<dim3(N_TOK / 64, H2DIM / 64, 2), 256>>>(hid2, hid2Bias);
    pair_kernel<<<dim3(N_TOK / 64, N_TOK / 64), 256>>>(outLayer, outBias, out);
}

// round 5
// speedup vs baseline: 1.0791x; 1.0788x over previous
#include <cuda_runtime.h>

#define N_TOK 1024
#define LDIM  256
#define HDIM  512
#define H2DIM 256

// scratch (allocation-free rule: __device__ globals)
__device__ float g_ah[N_TOK * HDIM];
__device__ float g_am[N_TOK * HDIM];
__device__ float g_At[H2DIM * N_TOK];   // A + hid2Bias, transposed [h2][i]
__device__ float g_Bt[H2DIM * N_TOK];   // B, transposed [h2][j]

__device__ __forceinline__ float tanh_apx(float x) {
    float y;
    asm("tanh.approx.f32 %0, %1;" : "=f"(y) : "f"(x));
    return y;
}

// ---------------------------------------------------------------------------
// P1: ah/am[i][h] = tanh( concat(l0,l1)[i,:] @ W[:,h] + catBias[z*H + h] )
// M=1024, N=512, K=512. Tile 32x64, BK=16, 128 threads, 4x4 micro.
// Double-buffered smem + register prefetch: 1 barrier per K-chunk, LDG
// latency overlapped with FFMAs. grid (32,8,2) = 512 CTAs -> ~3.5 CTAs/SM.
// ---------------------------------------------------------------------------
__global__ __launch_bounds__(128) void p1_kernel(
    const float* __restrict__ l0, const float* __restrict__ l1,
    const float* __restrict__ Wfoh, const float* __restrict__ Wfom,
    const float* __restrict__ catBias)
{
    const int z = blockIdx.z;
    const float* __restrict__ W = z ? Wfom : Wfoh;
    float* __restrict__ out = z ? g_am : g_ah;
    const int m0 = blockIdx.x * 32;
    const int n0 = blockIdx.y * 64;
    const int tid = threadIdx.x;
    const int tx = tid & 15, ty = tid >> 4;   // tx: 4 n's, ty: 4 m's (ty 0..7 -> 32 m)

    __shared__ float Xs[2][16][36];   // transposed [k][m]
    __shared__ float Ws[2][16][64];

    // loader indices
    const int xm = tid >> 2;            // 0..31 (m within tile)
    const int xk = (tid & 3) * 4;       // 0,4,8,12 (k within chunk)

    float acc[4][4] = {};
    float4 xreg;
    float4 wreg0, wreg1;

    const int NK = (2 * LDIM) / 16;     // 32 chunks

    // prefetch chunk 0
    {
        const float* __restrict__ src = l0;   // k0 = 0
        xreg = *(const float4*)&src[(m0 + xm) * LDIM + xk];
        int e0 = tid,       r0 = e0 >> 4, c0 = (e0 & 15) * 4;
        int e1 = tid + 128, r1 = e1 >> 4, c1 = (e1 & 15) * 4;
        wreg0 = *(const float4*)&W[r0 * HDIM + n0 + c0];
        wreg1 = *(const float4*)&W[r1 * HDIM + n0 + c1];
    }
    // store chunk 0
    Xs[0][xk + 0][xm] = xreg.x;
    Xs[0][xk + 1][xm] = xreg.y;
    Xs[0][xk + 2][xm] = xreg.z;
    Xs[0][xk + 3][xm] = xreg.w;
    {
        int e0 = tid,       r0 = e0 >> 4, c0 = (e0 & 15) * 4;
        int e1 = tid + 128, r1 = e1 >> 4, c1 = (e1 & 15) * 4;
        *(float4*)&Ws[0][r0][c0] = wreg0;
        *(float4*)&Ws[0][r1][c1] = wreg1;
    }
    __syncthreads();

    for (int c = 0; c < NK; c++) {
        const int cur = c & 1;
        const bool more = (c + 1 < NK);
        if (more) {
            const int k0 = (c + 1) * 16;
            const float* __restrict__ src =
                (k0 < LDIM) ? (l0 + k0) : (l1 + (k0 - LDIM));
            xreg = *(const float4*)&src[(m0 + xm) * LDIM + xk];
            int e0 = tid,       r0 = e0 >> 4, c0 = (e0 & 15) * 4;
            int e1 = tid + 128, r1 = e1 >> 4, c1 = (e1 & 15) * 4;
            wreg0 = *(const float4*)&W[(k0 + r0) * HDIM + n0 + c0];
            wreg1 = *(const float4*)&W[(k0 + r1) * HDIM + n0 + c1];
        }

        #pragma unroll
        for (int kk = 0; kk < 16; kk++) {
            float4 av = *(const float4*)&Xs[cur][kk][ty * 4];
            float4 bv = *(const float4*)&Ws[cur][kk][tx * 4];
            float a[4] = {av.x, av.y, av.z, av.w};
            float b[4] = {bv.x, bv.y, bv.z, bv.w};
            #pragma unroll
            for (int di = 0; di < 4; di++)
                #pragma unroll
                for (int dj = 0; dj < 4; dj++)
                    acc[di][dj] += a[di] * b[dj];
        }

        if (more) {
            const int nxt = 1 - cur;
            Xs[nxt][xk + 0][xm] = xreg.x;
            Xs[nxt][xk + 1][xm] = xreg.y;
            Xs[nxt][xk + 2][xm] = xreg.z;
            Xs[nxt][xk + 3][xm] = xreg.w;
            int e0 = tid,       r0 = e0 >> 4, c0 = (e0 & 15) * 4;
            int e1 = tid + 128, r1 = e1 >> 4, c1 = (e1 & 15) * 4;
            *(float4*)&Ws[nxt][r0][c0] = wreg0;
            *(float4*)&Ws[nxt][r1][c1] = wreg1;
            __syncthreads();
        }
    }

    const float* __restrict__ cb = catBias + z * HDIM + n0 + tx * 4;
    float b0 = cb[0], b1 = cb[1], b2 = cb[2], b3 = cb[3];
    #pragma unroll
    for (int di = 0; di < 4; di++) {
        int row = m0 + ty * 4 + di;
        float4 o;
        o.x = tanh_apx(acc[di][0] + b0);
        o.y = tanh_apx(acc[di][1] + b1);
        o.z = tanh_apx(acc[di][2] + b2);
        o.w = tanh_apx(acc[di][3] + b3);
        *(float4*)&out[row * HDIM + n0 + tx * 4] = o;
    }
}

// ---------------------------------------------------------------------------
// P2: At[h2][i] = ah[i,:] @ hid2[0:H, h2] + hid2Bias[h2]   (z=0)
//     Bt[h2][j] = am[j,:] @ hid2[H:2H, h2]                 (z=1)
// M=1024, N=256, K=512. Tile 32x64, BK=16, 128 threads, double-buffered.
// grid (32,4,2) = 256 CTAs. Output TRANSPOSED fp32.
// ---------------------------------------------------------------------------
__global__ __launch_bounds__(128) void p2_kernel(
    const float* __restrict__ hid2, const float* __restrict__ hid2Bias)
{
    const int z = blockIdx.z;
    const float* __restrict__ src = z ? g_am : g_ah;
    float* __restrict__ outp = z ? g_Bt : g_At;
    const int m0 = blockIdx.x * 32;
    const int n0 = blockIdx.y * 64;
    const int tid = threadIdx.x;
    const int tx = tid & 15, ty = tid >> 4;

    __shared__ float Xs[2][16][36];
    __shared__ float Ws[2][16][64];

    const int xm = tid >> 2;
    const int xk = (tid & 3) * 4;

    float acc[4][4] = {};
    float4 xreg;
    float4 wreg0, wreg1;

    const int NK = HDIM / 16;   // 32

    // prefetch chunk 0
    xreg = *(const float4*)&src[(m0 + xm) * HDIM + xk];
    {
        int e0 = tid,       r0 = e0 >> 4, c0 = (e0 & 15) * 4;
        int e1 = tid + 128, r1 = e1 >> 4, c1 = (e1 & 15) * 4;
        wreg0 = *(const float4*)&hid2[(z * HDIM + r0) * H2DIM + n0 + c0];
        wreg1 = *(const float4*)&hid2[(z * HDIM + r1) * H2DIM + n0 + c1];
    }
    Xs[0][xk + 0][xm] = xreg.x;
    Xs[0][xk + 1][xm] = xreg.y;
    Xs[0][xk + 2][xm] = xreg.z;
    Xs[0][xk + 3][xm] = xreg.w;
    {
        int e0 = tid,       r0 = e0 >> 4, c0 = (e0 & 15) * 4;
        int e1 = tid + 128, r1 = e1 >> 4, c1 = (e1 & 15) * 4;
        *(float4*)&Ws[0][r0][c0] = wreg0;
        *(float4*)&Ws[0][r1][c1] = wreg1;
    }
    __syncthreads();

    for (int c = 0; c < NK; c++) {
        const int cur = c & 1;
        const bool more = (c + 1 < NK);
        if (more) {
            const int k0 = (c + 1) * 16;
            xreg = *(const float4*)&src[(m0 + xm) * HDIM + k0 + xk];
            int e0 = tid,       r0 = e0 >> 4, c0 = (e0 & 15) * 4;
            int e1 = tid + 128, r1 = e1 >> 4, c1 = (e1 & 15) * 4;
            wreg0 = *(const float4*)&hid2[(z * HDIM + k0 + r0) * H2DIM + n0 + c0];
            wreg1 = *(const float4*)&hid2[(z * HDIM + k0 + r1) * H2DIM + n0 + c1];
        }

        #pragma unroll
        for (int kk = 0; kk < 16; kk++) {
            float4 av = *(const float4*)&Xs[cur][kk][ty * 4];
            float4 bv = *(const float4*)&Ws[cur][kk][tx * 4];
            float a[4] = {av.x, av.y, av.z, av.w};
            float b[4] = {bv.x, bv.y, bv.z, bv.w};
            #pragma unroll
            for (int di = 0; di < 4; di++)
                #pragma unroll
                for (int dj = 0; dj < 4; dj++)
                    acc[di][dj] += a[di] * b[dj];
        }

        if (more) {
            const int nxt = 1 - cur;
            Xs[nxt][xk + 0][xm] = xreg.x;
            Xs[nxt][xk + 1][xm] = xreg.y;
            Xs[nxt][xk + 2][xm] = xreg.z;
            Xs[nxt][xk + 3][xm] = xreg.w;
            int e0 = tid,       r0 = e0 >> 4, c0 = (e0 & 15) * 4;
            int e1 = tid + 128, r1 = e1 >> 4, c1 = (e1 & 15) * 4;
            *(float4*)&Ws[nxt][r0][c0] = wreg0;
            *(float4*)&Ws[nxt][r1][c1] = wreg1;
            __syncthreads();
        }
    }

    float bias[4] = {0.f, 0.f, 0.f, 0.f};
    if (z == 0) {
        #pragma unroll
        for (int dj = 0; dj < 4; dj++) bias[dj] = hid2Bias[n0 + tx * 4 + dj];
    }
    #pragma unroll
    for (int dj = 0; dj < 4; dj++) {
        int h2 = n0 + tx * 4 + dj;
        #pragma unroll
        for (int di = 0; di < 4; di++) {
            int i = m0 + ty * 4 + di;
            outp[h2 * N_TOK + i] = acc[di][dj] + bias[dj];
        }
    }
}

// ---------------------------------------------------------------------------
// Main pairwise kernel (fp32 — reverted from fp16; tanh.f16x2 gave no MUFU
// throughput gain on sm_103a while costing 7.6e-4 rel_err):
// scores[i][j] = outBias + sum_h tanh(At[h][i]+Bt[h][j]) * w[h]
// 64x64 CTA tile, 4x4 micro, h chunked by 64. grid 16x16 = 256 CTAs
// = one wave at 2 CTAs/SM. MUFU(tanh)-bound.
// ---------------------------------------------------------------------------
__global__ __launch_bounds__(256, 2) void pair_kernel(
    const float* __restrict__ outLayer, const float* __restrict__ outBias,
    float* __restrict__ out)
{
    const int j0 = blockIdx.x * 64;
    const int i0 = blockIdx.y * 64;
    const int tid = threadIdx.x;
    const int tx = tid & 15, ty = tid >> 4;

    __shared__ float sA[64][64];
    __shared__ float sB[64][64];
    __shared__ float sw[H2DIM];

    sw[tid] = outLayer[tid];   // tid covers 0..255 == H2DIM

    float acc[4][4] = {};

    for (int h0 = 0; h0 < H2DIM; h0 += 64) {
        #pragma unroll
        for (int q = 0; q < 4; q++) {
            int e = q * 256 + tid;          // float4 units, 1024 total
            int r = e >> 4, c4 = e & 15;
            *(float4*)&sA[r][c4 * 4] =
                *(const float4*)&g_At[(h0 + r) * N_TOK + i0 + c4 * 4];
            *(float4*)&sB[r][c4 * 4] =
                *(const float4*)&g_Bt[(h0 + r) * N_TOK + j0 + c4 * 4];
        }
        __syncthreads();

        #pragma unroll 16
        for (int hk = 0; hk < 64; hk++) {
            float4 av = *(const float4*)&sA[hk][ty * 4];
            float4 bv = *(const float4*)&sB[hk][tx * 4];
            float a[4] = {av.x, av.y, av.z, av.w};
            float b[4] = {bv.x, bv.y, bv.z, bv.w};
            float wv = sw[h0 + hk];
            #pragma unroll
            for (int di = 0; di < 4; di++)
                #pragma unroll
                for (int dj = 0; dj < 4; dj++)
                    acc[di][dj] += wv * tanh_apx(a[di] + b[dj]);
        }
        __syncthreads();
    }

    const float ob = outBias[0];
    #pragma unroll
    for (int di = 0; di < 4; di++) {
        int row = i0 + ty * 4 + di;
        float4 o;
        o.x = acc[di][0] + ob;
        o.y = acc[di][1] + ob;
        o.z = acc[di][2] + ob;
        o.w = acc[di][3] + ob;
        *(float4*)&out[row * N_TOK + j0 + tx * 4] = o;
    }
}

// ---------------------------------------------------------------------------
extern "C" void kernel_launch(void* const* d_in, const int* in_sizes, int n_in,
                              void* d_out, int out_size)
{
    const float* lstms0   = (const float*)d_in[0];  // [1024, 256]
    const float* lstms1   = (const float*)d_in[1];  // [1024, 256]
    const float* W_foh    = (const float*)d_in[2];  // [512, 512]
    const float* W_fom    = (const float*)d_in[3];  // [512, 512]
    const float* catBias  = (const float*)d_in[4];  // [1, 1024]
    const float* hid2     = (const float*)d_in[5];  // [1024, 256]
    const float* hid2Bias = (const float*)d_in[6];  // [1, 256]
    const float* outLayer = (const float*)d_in[7];  // [256, 1]
    const float* outBias  = (const float*)d_in[8];  // [1, 1]
    float* out = (float*)d_out;                     // [1024, 1024]

    p1_kernel<<<dim3(N_TOK / 32, HDIM / 64, 2), 128>>>(lstms0, lstms1, W_foh, W_fom, catBias);
    p2_kernel<<<dim3(N_TOK / 32, H2DIM / 64, 2), 128>>>(hid2, hid2Bias);
    pair_kernel<<<dim3(N_TOK / 64, N_TOK / 64), 256>>>(outLayer, outBias, out);
}

// round 6
// speedup vs baseline: 1.2487x; 1.1572x over previous
#include <cuda_runtime.h>

#define N_TOK 1024
#define LDIM  256
#define HDIM  512
#define H2DIM 256

// scratch (allocation-free rule: __device__ globals)
__device__ float g_ah[N_TOK * HDIM];
__device__ float g_am[N_TOK * HDIM];
__device__ float g_At[H2DIM * N_TOK];   // A + hid2Bias, transposed [h2][i]
__device__ float g_Bt[H2DIM * N_TOK];   // B, transposed [h2][j]

__device__ __forceinline__ float tanh_apx(float x) {
    float y;
    asm("tanh.approx.f32 %0, %1;" : "=f"(y) : "f"(x));
    return y;
}

__device__ __forceinline__ unsigned f2tf32(float x) {
    unsigned y;
    asm("cvt.rna.tf32.f32 %0, %1;" : "=r"(y) : "f"(x));
    return y;
}

// D += A(16x8) * B(8x8), tf32 inputs, fp32 accum
__device__ __forceinline__ void mma_tf32(float* d, const unsigned* a, const unsigned* b) {
    asm("mma.sync.aligned.m16n8k8.row.col.f32.tf32.tf32.f32 "
        "{%0,%1,%2,%3}, {%4,%5,%6,%7}, {%8,%9}, {%0,%1,%2,%3};"
        : "+f"(d[0]), "+f"(d[1]), "+f"(d[2]), "+f"(d[3])
        : "r"(a[0]), "r"(a[1]), "r"(a[2]), "r"(a[3]), "r"(b[0]), "r"(b[1]));
}

// ---------------------------------------------------------------------------
// P1 (tensor-core tf32): ah/am[i][h] = tanh( X[i,:] @ W[:,h] + catBias )
// M=1024, N=512, K=512. CTA 64x64, 128 thr (2x2 warps, 32x32 each), BK=32.
// grid (16,8,2) = 256 CTAs.
// ---------------------------------------------------------------------------
__global__ __launch_bounds__(128) void p1_kernel(
    const float* __restrict__ l0, const float* __restrict__ l1,
    const float* __restrict__ Wfoh, const float* __restrict__ Wfom,
    const float* __restrict__ catBias)
{
    const int z = blockIdx.z;
    const float* __restrict__ W = z ? Wfom : Wfoh;
    float* __restrict__ out = z ? g_am : g_ah;
    const int m0 = blockIdx.x * 64;
    const int n0 = blockIdx.y * 64;
    const int tid = threadIdx.x;
    const int lane = tid & 31, warp = tid >> 5;
    const int wm = warp & 1, wn = warp >> 1;
    const int lr = lane >> 2;     // 0..7
    const int lc = lane & 3;      // 0..3

    __shared__ unsigned Xs[64][36];   // [m][k] tf32 bits, pad 36: banks 4m+k distinct
    __shared__ unsigned Ws[32][72];   // [k][n] tf32 bits, pad 72: banks 8k+n distinct

    float C[2][4][4] = {};

    for (int k0 = 0; k0 < 2 * LDIM; k0 += 32) {
        const float* __restrict__ src = (k0 < LDIM) ? (l0 + k0) : (l1 + (k0 - LDIM));
        #pragma unroll
        for (int q = 0; q < 4; q++) {
            int e = q * 128 + tid;
            int row = e >> 3, c4 = (e & 7) * 4;
            float4 v = *(const float4*)&src[(m0 + row) * LDIM + c4];
            Xs[row][c4 + 0] = f2tf32(v.x);
            Xs[row][c4 + 1] = f2tf32(v.y);
            Xs[row][c4 + 2] = f2tf32(v.z);
            Xs[row][c4 + 3] = f2tf32(v.w);
        }
        #pragma unroll
        for (int q = 0; q < 4; q++) {
            int e = q * 128 + tid;
            int kr = e >> 4, c4 = (e & 15) * 4;
            float4 v = *(const float4*)&W[(k0 + kr) * HDIM + n0 + c4];
            Ws[kr][c4 + 0] = f2tf32(v.x);
            Ws[kr][c4 + 1] = f2tf32(v.y);
            Ws[kr][c4 + 2] = f2tf32(v.z);
            Ws[kr][c4 + 3] = f2tf32(v.w);
        }
        __syncthreads();

        #pragma unroll
        for (int ks = 0; ks < 32; ks += 8) {
            unsigned a[2][4], b[4][2];
            #pragma unroll
            for (int mt = 0; mt < 2; mt++) {
                int r = wm * 32 + mt * 16 + lr;
                a[mt][0] = Xs[r][ks + lc];
                a[mt][1] = Xs[r + 8][ks + lc];
                a[mt][2] = Xs[r][ks + lc + 4];
                a[mt][3] = Xs[r + 8][ks + lc + 4];
            }
            #pragma unroll
            for (int nt = 0; nt < 4; nt++) {
                int cn = wn * 32 + nt * 8 + lr;
                b[nt][0] = Ws[ks + lc][cn];
                b[nt][1] = Ws[ks + lc + 4][cn];
            }
            #pragma unroll
            for (int mt = 0; mt < 2; mt++)
                #pragma unroll
                for (int nt = 0; nt < 4; nt++)
                    mma_tf32(C[mt][nt], a[mt], b[nt]);
        }
        __syncthreads();
    }

    #pragma unroll
    for (int mt = 0; mt < 2; mt++) {
        #pragma unroll
        for (int nt = 0; nt < 4; nt++) {
            int row = m0 + wm * 32 + mt * 16 + lr;
            int col = n0 + wn * 32 + nt * 8 + 2 * lc;
            float cb0 = catBias[z * HDIM + col];
            float cb1 = catBias[z * HDIM + col + 1];
            out[row * HDIM + col]           = tanh_apx(C[mt][nt][0] + cb0);
            out[row * HDIM + col + 1]       = tanh_apx(C[mt][nt][1] + cb1);
            out[(row + 8) * HDIM + col]     = tanh_apx(C[mt][nt][2] + cb0);
            out[(row + 8) * HDIM + col + 1] = tanh_apx(C[mt][nt][3] + cb1);
        }
    }
}

// ---------------------------------------------------------------------------
// P2 (tensor-core tf32): At[h2][i] = ah[i,:]@hid2[0:H,h2] + hid2Bias  (z=0)
//                        Bt[h2][j] = am[j,:]@hid2[H:2H,h2]            (z=1)
// M=1024, N=256, K=512. Same structure. grid (16,4,2) = 128 CTAs.
// Output TRANSPOSED fp32.
// ---------------------------------------------------------------------------
__global__ __launch_bounds__(128) void p2_kernel(
    const float* __restrict__ hid2, const float* __restrict__ hid2Bias)
{
    const int z = blockIdx.z;
    const float* __restrict__ src = z ? g_am : g_ah;
    float* __restrict__ outp = z ? g_Bt : g_At;
    const int m0 = blockIdx.x * 64;
    const int n0 = blockIdx.y * 64;
    const int tid = threadIdx.x;
    const int lane = tid & 31, warp = tid >> 5;
    const int wm = warp & 1, wn = warp >> 1;
    const int lr = lane >> 2;
    const int lc = lane & 3;

    __shared__ unsigned Xs[64][36];
    __shared__ unsigned Ws[32][72];

    float C[2][4][4] = {};

    for (int k0 = 0; k0 < HDIM; k0 += 32) {
        #pragma unroll
        for (int q = 0; q < 4; q++) {
            int e = q * 128 + tid;
            int row = e >> 3, c4 = (e & 7) * 4;
            float4 v = *(const float4*)&src[(m0 + row) * HDIM + k0 + c4];
            Xs[row][c4 + 0] = f2tf32(v.x);
            Xs[row][c4 + 1] = f2tf32(v.y);
            Xs[row][c4 + 2] = f2tf32(v.z);
            Xs[row][c4 + 3] = f2tf32(v.w);
        }
        #pragma unroll
        for (int q = 0; q < 4; q++) {
            int e = q * 128 + tid;
            int kr = e >> 4, c4 = (e & 15) * 4;
            float4 v = *(const float4*)&hid2[(z * HDIM + k0 + kr) * H2DIM + n0 + c4];
            Ws[kr][c4 + 0] = f2tf32(v.x);
            Ws[kr][c4 + 1] = f2tf32(v.y);
            Ws[kr][c4 + 2] = f2tf32(v.z);
            Ws[kr][c4 + 3] = f2tf32(v.w);
        }
        __syncthreads();

        #pragma unroll
        for (int ks = 0; ks < 32; ks += 8) {
            unsigned a[2][4], b[4][2];
            #pragma unroll
            for (int mt = 0; mt < 2; mt++) {
                int r = wm * 32 + mt * 16 + lr;
                a[mt][0] = Xs[r][ks + lc];
                a[mt][1] = Xs[r + 8][ks + lc];
                a[mt][2] = Xs[r][ks + lc + 4];
                a[mt][3] = Xs[r + 8][ks + lc + 4];
            }
            #pragma unroll
            for (int nt = 0; nt < 4; nt++) {
                int cn = wn * 32 + nt * 8 + lr;
                b[nt][0] = Ws[ks + lc][cn];
                b[nt][1] = Ws[ks + lc + 4][cn];
            }
            #pragma unroll
            for (int mt = 0; mt < 2; mt++)
                #pragma unroll
                for (int nt = 0; nt < 4; nt++)
                    mma_tf32(C[mt][nt], a[mt], b[nt]);
        }
        __syncthreads();
    }

    #pragma unroll
    for (int mt = 0; mt < 2; mt++) {
        #pragma unroll
        for (int nt = 0; nt < 4; nt++) {
            int row = m0 + wm * 32 + mt * 16 + lr;     // token index
            int col = n0 + wn * 32 + nt * 8 + 2 * lc;  // h2 index
            float b0 = 0.f, b1 = 0.f;
            if (z == 0) { b0 = hid2Bias[col]; b1 = hid2Bias[col + 1]; }
            outp[col * N_TOK + row]           = C[mt][nt][0] + b0;
            outp[(col + 1) * N_TOK + row]     = C[mt][nt][1] + b1;
            outp[col * N_TOK + row + 8]       = C[mt][nt][2] + b0;
            outp[(col + 1) * N_TOK + row + 8] = C[mt][nt][3] + b1;
        }
    }
}

// ---------------------------------------------------------------------------
// Main pairwise kernel (fp32, at the MUFU floor for achieved clock):
// scores[i][j] = outBias + sum_h tanh(At[h][i]+Bt[h][j]) * w[h]
// 64x64 CTA tile, 4x4 micro. grid 16x16 = 256 CTAs.
// ---------------------------------------------------------------------------
__global__ __launch_bounds__(256, 2) void pair_kernel(
    const float* __restrict__ outLayer, const float* __restrict__ outBias,
    float* __restrict__ out)
{
    const int j0 = blockIdx.x * 64;
    const int i0 = blockIdx.y * 64;
    const int tid = threadIdx.x;
    const int tx = tid & 15, ty = tid >> 4;

    __shared__ float sA[64][64];
    __shared__ float sB[64][64];
    __shared__ float sw[H2DIM];

    sw[tid] = outLayer[tid];   // tid covers 0..255 == H2DIM

    float acc[4][4] = {};

    for (int h0 = 0; h0 < H2DIM; h0 += 64) {
        #pragma unroll
        for (int q = 0; q < 4; q++) {
            int e = q * 256 + tid;          // float4 units, 1024 total
            int r = e >> 4, c4 = e & 15;
            *(float4*)&sA[r][c4 * 4] =
                *(const float4*)&g_At[(h0 + r) * N_TOK + i0 + c4 * 4];
            *(float4*)&sB[r][c4 * 4] =
                *(const float4*)&g_Bt[(h0 + r) * N_TOK + j0 + c4 * 4];
        }
        __syncthreads();

        #pragma unroll 16
        for (int hk = 0; hk < 64; hk++) {
            float4 av = *(const float4*)&sA[hk][ty * 4];
            float4 bv = *(const float4*)&sB[hk][tx * 4];
            float a[4] = {av.x, av.y, av.z, av.w};
            float b[4] = {bv.x, bv.y, bv.z, bv.w};
            float wv = sw[h0 + hk];
            #pragma unroll
            for (int di = 0; di < 4; di++)
                #pragma unroll
                for (int dj = 0; dj < 4; dj++)
                    acc[di][dj] += wv * tanh_apx(a[di] + b[dj]);
        }
        __syncthreads();
    }

    const float ob = outBias[0];
    #pragma unroll
    for (int di = 0; di < 4; di++) {
        int row = i0 + ty * 4 + di;
        float4 o;
        o.x = acc[di][0] + ob;
        o.y = acc[di][1] + ob;
        o.z = acc[di][2] + ob;
        o.w = acc[di][3] + ob;
        *(float4*)&out[row * N_TOK + j0 + tx * 4] = o;
    }
}

// ---------------------------------------------------------------------------
extern "C" void kernel_launch(void* const* d_in, const int* in_sizes, int n_in,
                              void* d_out, int out_size)
{
    const float* lstms0   = (const float*)d_in[0];  // [1024, 256]
    const float* lstms1   = (const float*)d_in[1];  // [1024, 256]
    const float* W_foh    = (const float*)d_in[2];  // [512, 512]
    const float* W_fom    = (const float*)d_in[3];  // [512, 512]
    const float* catBias  = (const float*)d_in[4];  // [1, 1024]
    const float* hid2     = (const float*)d_in[5];  // [1024, 256]
    const float* hid2Bias = (const float*)d_in[6];  // [1, 256]
    const float* outLayer = (const float*)d_in[7];  // [256, 1]
    const float* outBias  = (const float*)d_in[8];  // [1, 1]
    float* out = (float*)d_out;                     // [1024, 1024]

    p1_kernel<<<dim3(N_TOK / 64, HDIM / 64, 2), 128>>>(lstms0, lstms1, W_foh, W_fom, catBias);
    p2_kernel<<<dim3(N_TOK / 64, H2DIM / 64, 2), 128>>>(hid2, hid2Bias);
    pair_kernel<<<dim3(N_TOK / 64, N_TOK / 64), 256>>>(outLayer, outBias, out);
}

// round 8
// speedup vs baseline: 1.3791x; 1.1044x over previous
#include <cuda_runtime.h>

#define N_TOK 1024
#define LDIM  256
#define HDIM  512
#define H2DIM 256

// scratch (allocation-free rule: __device__ globals)
__device__ float g_ah[N_TOK * HDIM];
__device__ float g_am[N_TOK * HDIM];
__device__ float g_At[H2DIM * N_TOK];   // A + hid2Bias, transposed [h2][i]
__device__ float g_Bt[H2DIM * N_TOK];   // B, transposed [h2][j]

__device__ __forceinline__ float tanh_apx(float x) {
    float y;
    asm("tanh.approx.f32 %0, %1;" : "=f"(y) : "f"(x));
    return y;
}

__device__ __forceinline__ unsigned f2tf32(float x) {
    unsigned y;
    asm("cvt.rna.tf32.f32 %0, %1;" : "=r"(y) : "f"(x));
    return y;
}

// D += A(16x8) * B(8x8), tf32 inputs, fp32 accum
__device__ __forceinline__ void mma_tf32(float* d, const unsigned* a, const unsigned* b) {
    asm("mma.sync.aligned.m16n8k8.row.col.f32.tf32.tf32.f32 "
        "{%0,%1,%2,%3}, {%4,%5,%6,%7}, {%8,%9}, {%0,%1,%2,%3};"
        : "+f"(d[0]), "+f"(d[1]), "+f"(d[2]), "+f"(d[3])
        : "r"(a[0]), "r"(a[1]), "r"(a[2]), "r"(a[3]), "r"(b[0]), "r"(b[1]));
}

// ---------------------------------------------------------------------------
// P1 (tf32 MMA, double-buffered): ah/am[i][h] = tanh(X[i,:]@W[:,h] + catBias)
// M=1024, N=512, K=512. CTA 64x64, 256 thr (8 warps: 4 m-chunks x 2 n-chunks,
// each warp 16x32), BK=32, 2-stage smem + register prefetch.
// grid (16,8,2) = 256 CTAs.
// ---------------------------------------------------------------------------
__global__ __launch_bounds__(256) void p1_kernel(
    const float* __restrict__ l0, const float* __restrict__ l1,
    const float* __restrict__ Wfoh, const float* __restrict__ Wfom,
    const float* __restrict__ catBias)
{
    const int z = blockIdx.z;
    const float* __restrict__ W = z ? Wfom : Wfoh;
    float* __restrict__ out = z ? g_am : g_ah;
    const int m0 = blockIdx.x * 64;
    const int n0 = blockIdx.y * 64;
    const int tid = threadIdx.x;
    const int lane = tid & 31, warp = tid >> 5;
    const int wm = warp & 3;       // 4 m-chunks of 16
    const int wn = warp >> 2;      // 2 n-chunks of 32
    const int lr = lane >> 2;      // 0..7
    const int lc = lane & 3;       // 0..3

    __shared__ unsigned Xs[2][64][36];   // [m][k] tf32 bits; LDS bank = lr*4+lc (bijective)
    __shared__ unsigned Ws[2][32][72];   // [k][n] tf32 bits; LDS bank = lc*8+lr (bijective)

    // loader indices (2 float4 per thread per tile)
    const int xrow0 = tid >> 3, xc4 = (tid & 7) * 4;   // e = tid      -> rows 0..31
    const int xrow1 = xrow0 + 32;                      // e = tid+256  -> rows 32..63
    const int wkr0 = tid >> 4, wc4 = (tid & 15) * 4;   // k-rows 0..15
    const int wkr1 = wkr0 + 16;                        // k-rows 16..31

    float C[4][4] = {};
    float4 xr0, xr1, wr0, wr1;

    const int NK = (2 * LDIM) / 32;   // 16 chunks; 256-elem seam is chunk-aligned

    auto load_chunk = [&](int k0) {
        const float* __restrict__ src = (k0 < LDIM) ? (l0 + k0) : (l1 + (k0 - LDIM));
        xr0 = *(const float4*)&src[(m0 + xrow0) * LDIM + xc4];
        xr1 = *(const float4*)&src[(m0 + xrow1) * LDIM + xc4];
        wr0 = *(const float4*)&W[(k0 + wkr0) * HDIM + n0 + wc4];
        wr1 = *(const float4*)&W[(k0 + wkr1) * HDIM + n0 + wc4];
    };
    auto store_chunk = [&](int buf) {
        Xs[buf][xrow0][xc4 + 0] = f2tf32(xr0.x);
        Xs[buf][xrow0][xc4 + 1] = f2tf32(xr0.y);
        Xs[buf][xrow0][xc4 + 2] = f2tf32(xr0.z);
        Xs[buf][xrow0][xc4 + 3] = f2tf32(xr0.w);
        Xs[buf][xrow1][xc4 + 0] = f2tf32(xr1.x);
        Xs[buf][xrow1][xc4 + 1] = f2tf32(xr1.y);
        Xs[buf][xrow1][xc4 + 2] = f2tf32(xr1.z);
        Xs[buf][xrow1][xc4 + 3] = f2tf32(xr1.w);
        Ws[buf][wkr0][wc4 + 0] = f2tf32(wr0.x);
        Ws[buf][wkr0][wc4 + 1] = f2tf32(wr0.y);
        Ws[buf][wkr0][wc4 + 2] = f2tf32(wr0.z);
        Ws[buf][wkr0][wc4 + 3] = f2tf32(wr0.w);
        Ws[buf][wkr1][wc4 + 0] = f2tf32(wr1.x);
        Ws[buf][wkr1][wc4 + 1] = f2tf32(wr1.y);
        Ws[buf][wkr1][wc4 + 2] = f2tf32(wr1.z);
        Ws[buf][wkr1][wc4 + 3] = f2tf32(wr1.w);
    };

    load_chunk(0);
    store_chunk(0);
    __syncthreads();

    for (int c = 0; c < NK; c++) {
        const int cur = c & 1;
        const bool more = (c + 1 < NK);
        if (more) load_chunk((c + 1) * 32);

        #pragma unroll
        for (int ks = 0; ks < 32; ks += 8) {
            unsigned a[4], b[4][2];
            const int r = wm * 16 + lr;
            a[0] = Xs[cur][r][ks + lc];
            a[1] = Xs[cur][r + 8][ks + lc];
            a[2] = Xs[cur][r][ks + lc + 4];
            a[3] = Xs[cur][r + 8][ks + lc + 4];
            #pragma unroll
            for (int nt = 0; nt < 4; nt++) {
                int cn = wn * 32 + nt * 8 + lr;
                b[nt][0] = Ws[cur][ks + lc][cn];
                b[nt][1] = Ws[cur][ks + lc + 4][cn];
            }
            #pragma unroll
            for (int nt = 0; nt < 4; nt++)
                mma_tf32(C[nt], a, b[nt]);
        }

        if (more) {
            store_chunk(1 - cur);
            __syncthreads();
        }
    }

    #pragma unroll
    for (int nt = 0; nt < 4; nt++) {
        int row = m0 + wm * 16 + lr;
        int col = n0 + wn * 32 + nt * 8 + 2 * lc;
        float cb0 = catBias[z * HDIM + col];
        float cb1 = catBias[z * HDIM + col + 1];
        out[row * HDIM + col]           = tanh_apx(C[nt][0] + cb0);
        out[row * HDIM + col + 1]       = tanh_apx(C[nt][1] + cb1);
        out[(row + 8) * HDIM + col]     = tanh_apx(C[nt][2] + cb0);
        out[(row + 8) * HDIM + col + 1] = tanh_apx(C[nt][3] + cb1);
    }
}

// ---------------------------------------------------------------------------
// P2 (tf32 MMA, double-buffered): At[h2][i] = ah[i,:]@hid2[0:H,h2]+bias (z=0)
//                                 Bt[h2][j] = am[j,:]@hid2[H:2H,h2]    (z=1)
// M=1024, N=256, K=512. Same structure as P1. grid (16,4,2) = 128 CTAs.
// Output TRANSPOSED fp32.
// ---------------------------------------------------------------------------
__global__ __launch_bounds__(256) void p2_kernel(
    const float* __restrict__ hid2, const float* __restrict__ hid2Bias)
{
    const int z = blockIdx.z;
    const float* __restrict__ src = z ? g_am : g_ah;
    float* __restrict__ outp = z ? g_Bt : g_At;
    const int m0 = blockIdx.x * 64;
    const int n0 = blockIdx.y * 64;
    const int tid = threadIdx.x;
    const int lane = tid & 31, warp = tid >> 5;
    const int wm = warp & 3;
    const int wn = warp >> 2;
    const int lr = lane >> 2;
    const int lc = lane & 3;

    __shared__ unsigned Xs[2][64][36];
    __shared__ unsigned Ws[2][32][72];

    const int xrow0 = tid >> 3, xc4 = (tid & 7) * 4;
    const int xrow1 = xrow0 + 32;
    const int wkr0 = tid >> 4, wc4 = (tid & 15) * 4;
    const int wkr1 = wkr0 + 16;

    float C[4][4] = {};
    float4 xr0, xr1, wr0, wr1;

    const int NK = HDIM / 32;   // 16

    auto load_chunk = [&](int k0) {
        xr0 = *(const float4*)&src[(m0 + xrow0) * HDIM + k0 + xc4];
        xr1 = *(const float4*)&src[(m0 + xrow1) * HDIM + k0 + xc4];
        wr0 = *(const float4*)&hid2[(z * HDIM + k0 + wkr0) * H2DIM + n0 + wc4];
        wr1 = *(const float4*)&hid2[(z * HDIM + k0 + wkr1) * H2DIM + n0 + wc4];
    };
    auto store_chunk = [&](int buf) {
        Xs[buf][xrow0][xc4 + 0] = f2tf32(xr0.x);
        Xs[buf][xrow0][xc4 + 1] = f2tf32(xr0.y);
        Xs[buf][xrow0][xc4 + 2] = f2tf32(xr0.z);
        Xs[buf][xrow0][xc4 + 3] = f2tf32(xr0.w);
        Xs[buf][xrow1][xc4 + 0] = f2tf32(xr1.x);
        Xs[buf][xrow1][xc4 + 1] = f2tf32(xr1.y);
        Xs[buf][xrow1][xc4 + 2] = f2tf32(xr1.z);
        Xs[buf][xrow1][xc4 + 3] = f2tf32(xr1.w);
        Ws[buf][wkr0][wc4 + 0] = f2tf32(wr0.x);
        Ws[buf][wkr0][wc4 + 1] = f2tf32(wr0.y);
        Ws[buf][wkr0][wc4 + 2] = f2tf32(wr0.z);
        Ws[buf][wkr0][wc4 + 3] = f2tf32(wr0.w);
        Ws[buf][wkr1][wc4 + 0] = f2tf32(wr1.x);
        Ws[buf][wkr1][wc4 + 1] = f2tf32(wr1.y);
        Ws[buf][wkr1][wc4 + 2] = f2tf32(wr1.z);
        Ws[buf][wkr1][wc4 + 3] = f2tf32(wr1.w);
    };

    load_chunk(0);
    store_chunk(0);
    __syncthreads();

    for (int c = 0; c < NK; c++) {
        const int cur = c & 1;
        const bool more = (c + 1 < NK);
        if (more) load_chunk((c + 1) * 32);

        #pragma unroll
        for (int ks = 0; ks < 32; ks += 8) {
            unsigned a[4], b[4][2];
            const int r = wm * 16 + lr;
            a[0] = Xs[cur][r][ks + lc];
            a[1] = Xs[cur][r + 8][ks + lc];
            a[2] = Xs[cur][r][ks + lc + 4];
            a[3] = Xs[cur][r + 8][ks + lc + 4];
            #pragma unroll
            for (int nt = 0; nt < 4; nt++) {
                int cn = wn * 32 + nt * 8 + lr;
                b[nt][0] = Ws[cur][ks + lc][cn];
                b[nt][1] = Ws[cur][ks + lc + 4][cn];
            }
            #pragma unroll
            for (int nt = 0; nt < 4; nt++)
                mma_tf32(C[nt], a, b[nt]);
        }

        if (more) {
            store_chunk(1 - cur);
            __syncthreads();
        }
    }

    #pragma unroll
    for (int nt = 0; nt < 4; nt++) {
        int row = m0 + wm * 16 + lr;               // token index
        int col = n0 + wn * 32 + nt * 8 + 2 * lc;  // h2 index
        float b0 = 0.f, b1 = 0.f;
        if (z == 0) { b0 = hid2Bias[col]; b1 = hid2Bias[col + 1]; }
        outp[col * N_TOK + row]           = C[nt][0] + b0;
        outp[(col + 1) * N_TOK + row]     = C[nt][1] + b1;
        outp[col * N_TOK + row + 8]       = C[nt][2] + b0;
        outp[(col + 1) * N_TOK + row + 8] = C[nt][3] + b1;
    }
}

// ---------------------------------------------------------------------------
// Main pairwise kernel (fp32, at the MUFU floor):
// scores[i][j] = outBias + sum_h tanh(At[h][i]+Bt[h][j]) * w[h]
// 64x64 CTA tile, 4x4 micro. grid 16x16 = 256 CTAs.
// ---------------------------------------------------------------------------
__global__ __launch_bounds__(256, 2) void pair_kernel(
    const float* __restrict__ outLayer, const float* __restrict__ outBias,
    float* __restrict__ out)
{
    const int j0 = blockIdx.x * 64;
    const int i0 = blockIdx.y * 64;
    const int tid = threadIdx.x;
    const int tx = tid & 15, ty = tid >> 4;

    __shared__ float sA[64][64];
    __shared__ float sB[64][64];
    __shared__ float sw[H2DIM];

    sw[tid] = outLayer[tid];   // tid covers 0..255 == H2DIM

    float acc[4][4] = {};

    for (int h0 = 0; h0 < H2DIM; h0 += 64) {
        #pragma unroll
        for (int q = 0; q < 4; q++) {
            int e = q * 256 + tid;          // float4 units, 1024 total
            int r = e >> 4, c4 = e & 15;
            *(float4*)&sA[r][c4 * 4] =
                *(const float4*)&g_At[(h0 + r) * N_TOK + i0 + c4 * 4];
            *(float4*)&sB[r][c4 * 4] =
                *(const float4*)&g_Bt[(h0 + r) * N_TOK + j0 + c4 * 4];
        }
        __syncthreads();

        #pragma unroll 16
        for (int hk = 0; hk < 64; hk++) {
            float4 av = *(const float4*)&sA[hk][ty * 4];
            float4 bv = *(const float4*)&sB[hk][tx * 4];
            float a[4] = {av.x, av.y, av.z, av.w};
            float b[4] = {bv.x, bv.y, bv.z, bv.w};
            float wv = sw[h0 + hk];
            #pragma unroll
            for (int di = 0; di < 4; di++)
                #pragma unroll
                for (int dj = 0; dj < 4; dj++)
                    acc[di][dj] += wv * tanh_apx(a[di] + b[dj]);
        }
        __syncthreads();
    }

    const float ob = outBias[0];
    #pragma unroll
    for (int di = 0; di < 4; di++) {
        int row = i0 + ty * 4 + di;
        float4 o;
        o.x = acc[di][0] + ob;
        o.y = acc[di][1] + ob;
        o.z = acc[di][2] + ob;
        o.w = acc[di][3] + ob;
        *(float4*)&out[row * N_TOK + j0 + tx * 4] = o;
    }
}

// ---------------------------------------------------------------------------
extern "C" void kernel_launch(void* const* d_in, const int* in_sizes, int n_in,
                              void* d_out, int out_size)
{
    const float* lstms0   = (const float*)d_in[0];  // [1024, 256]
    const float* lstms1   = (const float*)d_in[1];  // [1024, 256]
    const float* W_foh    = (const float*)d_in[2];  // [512, 512]
    const float* W_fom    = (const float*)d_in[3];  // [512, 512]
    const float* catBias  = (const float*)d_in[4];  // [1, 1024]
    const float* hid2     = (const float*)d_in[5];  // [1024, 256]
    const float* hid2Bias = (const float*)d_in[6];  // [1, 256]
    const float* outLayer = (const float*)d_in[7];  // [256, 1]
    const float* outBias  = (const float*)d_in[8];  // [1, 1]
    float* out = (float*)d_out;                     // [1024, 1024]

    p1_kernel<<<dim3(N_TOK / 64, HDIM / 64, 2), 256>>>(lstms0, lstms1, W_foh, W_fom, catBias);
    p2_kernel<<<dim3(N_TOK / 64, H2DIM / 64, 2), 256>>>(hid2, hid2Bias);
    pair_kernel<<<dim3(N_TOK / 64, N_TOK / 64), 256>>>(outLayer, outBias, out);
}

// round 9
// speedup vs baseline: 1.4590x; 1.0580x over previous
#include <cuda_runtime.h>

#define N_TOK 1024
#define LDIM  256
#define HDIM  512
#define H2DIM 256

// scratch (allocation-free rule: __device__ globals)
__device__ float g_xr[N_TOK * HDIM];          // concat(l0,l1), tf32-rounded
__device__ float g_wr[2 * HDIM * HDIM];       // W_foh | W_fom, tf32-rounded
__device__ float g_h2r[2 * HDIM * H2DIM];     // hid2, tf32-rounded
__device__ float g_ah[N_TOK * HDIM];          // tanh outputs, tf32-rounded
__device__ float g_am[N_TOK * HDIM];
__device__ float g_At[H2DIM * N_TOK];         // A + hid2Bias, transposed [h2][i]
__device__ float g_Bt[H2DIM * N_TOK];         // B, transposed [h2][j]

__device__ __forceinline__ float tanh_apx(float x) {
    float y;
    asm("tanh.approx.f32 %0, %1;" : "=f"(y) : "f"(x));
    return y;
}

__device__ __forceinline__ unsigned f2tf32(float x) {
    unsigned y;
    asm("cvt.rna.tf32.f32 %0, %1;" : "=r"(y) : "f"(x));
    return y;
}

__device__ __forceinline__ float rnd_tf32(float x) {
    return __uint_as_float(f2tf32(x));
}

__device__ __forceinline__ float4 rnd4(float4 v) {
    float4 r;
    r.x = rnd_tf32(v.x); r.y = rnd_tf32(v.y);
    r.z = rnd_tf32(v.z); r.w = rnd_tf32(v.w);
    return r;
}

// D += A(16x8) * B(8x8), tf32 inputs, fp32 accum
__device__ __forceinline__ void mma_tf32(float* d, const unsigned* a, const unsigned* b) {
    asm("mma.sync.aligned.m16n8k8.row.col.f32.tf32.tf32.f32 "
        "{%0,%1,%2,%3}, {%4,%5,%6,%7}, {%8,%9}, {%0,%1,%2,%3};"
        : "+f"(d[0]), "+f"(d[1]), "+f"(d[2]), "+f"(d[3])
        : "r"(a[0]), "r"(a[1]), "r"(a[2]), "r"(a[3]), "r"(b[0]), "r"(b[1]));
}

__device__ __forceinline__ void cp16(void* dst_smem, const void* src_gmem) {
    unsigned d = (unsigned)__cvta_generic_to_shared(dst_smem);
    asm volatile("cp.async.cg.shared.global [%0], [%1], 16;\n"
                 :: "r"(d), "l"(src_gmem));
}
#define CP_COMMIT()  asm volatile("cp.async.commit_group;\n" ::: "memory")
#define CP_WAIT(n)   asm volatile("cp.async.wait_group %0;\n" :: "n"(n) : "memory")

// ---------------------------------------------------------------------------
// Pre-pass: tf32-round X (concat), W_foh/W_fom, hid2 into device buffers.
// Pure bandwidth (~10MB), float4 grid-stride.
// ---------------------------------------------------------------------------
__global__ __launch_bounds__(256) void prep_kernel(
    const float* __restrict__ l0, const float* __restrict__ l1,
    const float* __restrict__ Wfoh, const float* __restrict__ Wfom,
    const float* __restrict__ hid2)
{
    const int nt = gridDim.x * blockDim.x;
    const int t0 = blockIdx.x * blockDim.x + threadIdx.x;

    // X: 1024 rows x 128 float4 (first 64 from l0, next 64 from l1)
    for (int e = t0; e < N_TOK * 128; e += nt) {
        int i = e >> 7, c = e & 127;
        float4 v = (c < 64) ? ((const float4*)l0)[i * 64 + c]
                            : ((const float4*)l1)[i * 64 + (c - 64)];
        ((float4*)g_xr)[e] = rnd4(v);
    }
    // W: 2 x 65536 float4
    for (int e = t0; e < 2 * 65536; e += nt) {
        float4 v = (e < 65536) ? ((const float4*)Wfoh)[e]
                               : ((const float4*)Wfom)[e - 65536];
        ((float4*)g_wr)[e] = rnd4(v);
    }
    // hid2: 65536 float4
    for (int e = t0; e < 65536; e += nt) {
        ((float4*)g_h2r)[e] = rnd4(((const float4*)hid2)[e]);
    }
}

// ---------------------------------------------------------------------------
// P1 (tf32 MMA, cp.async 2-stage): ah/am[i][h] = tanh(X@W + catBias), rounded
// to tf32 on store. CTA 64x64, 256 thr (8 warps, 16x32 each), BK=32.
// grid (16,8,2) = 256 CTAs. All smem fills are 16B LDGSTS, no CVT/STS.
// ---------------------------------------------------------------------------
__global__ __launch_bounds__(256) void p1_kernel(const float* __restrict__ catBias)
{
    const int z = blockIdx.z;
    const float* __restrict__ W = g_wr + z * HDIM * HDIM;
    float* __restrict__ out = z ? g_am : g_ah;
    const int m0 = blockIdx.x * 64;
    const int n0 = blockIdx.y * 64;
    const int tid = threadIdx.x;
    const int lane = tid & 31, warp = tid >> 5;
    const int wm = warp & 3;       // 4 m-chunks of 16
    const int wn = warp >> 2;      // 2 n-chunks of 32
    const int lr = lane >> 2;      // 0..7
    const int lc = lane & 3;       // 0..3

    __shared__ float Xs[2][64][36];   // [m][k]; LDS bank = lr*4+lc (bijective)
    __shared__ float Ws[2][32][72];   // [k][n]; LDS bank = lc*8+lr (bijective)

    // copy slot indices (2 X-chunks + 2 W-chunks of 16B per thread per stage)
    const int xrow0 = tid >> 3, xc4 = (tid & 7) * 4;   // rows 0..31
    const int xrow1 = xrow0 + 32;                      // rows 32..63
    const int wkr0 = tid >> 4, wc4 = (tid & 15) * 4;   // k-rows 0..15
    const int wkr1 = wkr0 + 16;                        // k-rows 16..31

    const int NK = HDIM / 32;   // 16 chunks

    auto issue = [&](int buf, int k0) {
        cp16(&Xs[buf][xrow0][xc4], &g_xr[(m0 + xrow0) * HDIM + k0 + xc4]);
        cp16(&Xs[buf][xrow1][xc4], &g_xr[(m0 + xrow1) * HDIM + k0 + xc4]);
        cp16(&Ws[buf][wkr0][wc4], &W[(k0 + wkr0) * HDIM + n0 + wc4]);
        cp16(&Ws[buf][wkr1][wc4], &W[(k0 + wkr1) * HDIM + n0 + wc4]);
        CP_COMMIT();
    };

    float C[4][4] = {};

    issue(0, 0);
    for (int c = 0; c < NK; c++) {
        const int cur = c & 1;
        if (c + 1 < NK) {
            issue(1 - cur, (c + 1) * 32);
            CP_WAIT(1);
        } else {
            CP_WAIT(0);
        }
        __syncthreads();

        #pragma unroll
        for (int ks = 0; ks < 32; ks += 8) {
            unsigned a[4], b[4][2];
            const int r = wm * 16 + lr;
            a[0] = __float_as_uint(Xs[cur][r][ks + lc]);
            a[1] = __float_as_uint(Xs[cur][r + 8][ks + lc]);
            a[2] = __float_as_uint(Xs[cur][r][ks + lc + 4]);
            a[3] = __float_as_uint(Xs[cur][r + 8][ks + lc + 4]);
            #pragma unroll
            for (int nt = 0; nt < 4; nt++) {
                int cn = wn * 32 + nt * 8 + lr;
                b[nt][0] = __float_as_uint(Ws[cur][ks + lc][cn]);
                b[nt][1] = __float_as_uint(Ws[cur][ks + lc + 4][cn]);
            }
            #pragma unroll
            for (int nt = 0; nt < 4; nt++)
                mma_tf32(C[nt], a, b[nt]);
        }
        __syncthreads();   // protect buffer (1-cur) before next issue overwrites
    }

    #pragma unroll
    for (int nt = 0; nt < 4; nt++) {
        int row = m0 + wm * 16 + lr;
        int col = n0 + wn * 32 + nt * 8 + 2 * lc;
        float cb0 = catBias[z * HDIM + col];
        float cb1 = catBias[z * HDIM + col + 1];
        out[row * HDIM + col]           = rnd_tf32(tanh_apx(C[nt][0] + cb0));
        out[row * HDIM + col + 1]       = rnd_tf32(tanh_apx(C[nt][1] + cb1));
        out[(row + 8) * HDIM + col]     = rnd_tf32(tanh_apx(C[nt][2] + cb0));
        out[(row + 8) * HDIM + col + 1] = rnd_tf32(tanh_apx(C[nt][3] + cb1));
    }
}

// ---------------------------------------------------------------------------
// P2 (tf32 MMA, cp.async 2-stage): At[h2][i] = ah@hid2[0:H] + bias  (z=0)
//                                  Bt[h2][j] = am@hid2[H:2H]        (z=1)
// CTA 32x64, 128 thr (4 warps: wm 2 x wn 2, each 16x32), BK=32.
// grid (32,4,2) = 256 CTAs. Output TRANSPOSED fp32.
// ---------------------------------------------------------------------------
__global__ __launch_bounds__(128) void p2_kernel(const float* __restrict__ hid2Bias)
{
    const int z = blockIdx.z;
    const float* __restrict__ src = z ? g_am : g_ah;
    const float* __restrict__ W = g_h2r + z * HDIM * H2DIM;
    float* __restrict__ outp = z ? g_Bt : g_At;
    const int m0 = blockIdx.x * 32;
    const int n0 = blockIdx.y * 64;
    const int tid = threadIdx.x;
    const int lane = tid & 31, warp = tid >> 5;
    const int wm = warp & 1;       // 2 m-chunks of 16
    const int wn = warp >> 1;      // 2 n-chunks of 32
    const int lr = lane >> 2;
    const int lc = lane & 3;

    __shared__ float Xs[2][32][36];
    __shared__ float Ws[2][32][72];

    // X: 32x32 = 256 16B-chunks -> 2/thread; W: 32x64 = 512 -> 4/thread
    const int xrow0 = tid >> 3, xc4 = (tid & 7) * 4;   // rows 0..15
    const int xrow1 = xrow0 + 16;                      // rows 16..31
    const int wkr = tid >> 4, wc4 = (tid & 15) * 4;    // k-rows 0..7 (+8,+16,+24)

    const int NK = HDIM / 32;   // 16

    auto issue = [&](int buf, int k0) {
        cp16(&Xs[buf][xrow0][xc4], &src[(m0 + xrow0) * HDIM + k0 + xc4]);
        cp16(&Xs[buf][xrow1][xc4], &src[(m0 + xrow1) * HDIM + k0 + xc4]);
        #pragma unroll
        for (int q = 0; q < 4; q++)
            cp16(&Ws[buf][wkr + q * 8][wc4],
                 &W[(k0 + wkr + q * 8) * H2DIM + n0 + wc4]);
        CP_COMMIT();
    };

    float C[4][4] = {};

    issue(0, 0);
    for (int c = 0; c < NK; c++) {
        const int cur = c & 1;
        if (c + 1 < NK) {
            issue(1 - cur, (c + 1) * 32);
            CP_WAIT(1);
        } else {
            CP_WAIT(0);
        }
        __syncthreads();

        #pragma unroll
        for (int ks = 0; ks < 32; ks += 8) {
            unsigned a[4], b[4][2];
            const int r = wm * 16 + lr;
            a[0] = __float_as_uint(Xs[cur][r][ks + lc]);
            a[1] = __float_as_uint(Xs[cur][r + 8][ks + lc]);
            a[2] = __float_as_uint(Xs[cur][r][ks + lc + 4]);
            a[3] = __float_as_uint(Xs[cur][r + 8][ks + lc + 4]);
            #pragma unroll
            for (int nt = 0; nt < 4; nt++) {
                int cn = wn * 32 + nt * 8 + lr;
                b[nt][0] = __float_as_uint(Ws[cur][ks + lc][cn]);
                b[nt][1] = __float_as_uint(Ws[cur][ks + lc + 4][cn]);
            }
            #pragma unroll
            for (int nt = 0; nt < 4; nt++)
                mma_tf32(C[nt], a, b[nt]);
        }
        __syncthreads();
    }

    #pragma unroll
    for (int nt = 0; nt < 4; nt++) {
        int row = m0 + wm * 16 + lr;               // token index
        int col = n0 + wn * 32 + nt * 8 + 2 * lc;  // h2 index
        float b0 = 0.f, b1 = 0.f;
        if (z == 0) { b0 = hid2Bias[col]; b1 = hid2Bias[col + 1]; }
        outp[col * N_TOK + row]           = C[nt][0] + b0;
        outp[(col + 1) * N_TOK + row]     = C[nt][1] + b1;
        outp[col * N_TOK + row + 8]       = C[nt][2] + b0;
        outp[(col + 1) * N_TOK + row + 8] = C[nt][3] + b1;
    }
}

// ---------------------------------------------------------------------------
// Main pairwise kernel (fp32, at the MUFU floor):
// scores[i][j] = outBias + sum_h tanh(At[h][i]+Bt[h][j]) * w[h]
// 64x64 CTA tile, 4x4 micro. grid 16x16 = 256 CTAs.
// ---------------------------------------------------------------------------
__global__ __launch_bounds__(256, 2) void pair_kernel(
    const float* __restrict__ outLayer, const float* __restrict__ outBias,
    float* __restrict__ out)
{
    const int j0 = blockIdx.x * 64;
    const int i0 = blockIdx.y * 64;
    const int tid = threadIdx.x;
    const int tx = tid & 15, ty = tid >> 4;

    __shared__ float sA[64][64];
    __shared__ float sB[64][64];
    __shared__ float sw[H2DIM];

    sw[tid] = outLayer[tid];   // tid covers 0..255 == H2DIM

    float acc[4][4] = {};

    for (int h0 = 0; h0 < H2DIM; h0 += 64) {
        #pragma unroll
        for (int q = 0; q < 4; q++) {
            int e = q * 256 + tid;          // float4 units, 1024 total
            int r = e >> 4, c4 = e & 15;
            *(float4*)&sA[r][c4 * 4] =
                *(const float4*)&g_At[(h0 + r) * N_TOK + i0 + c4 * 4];
            *(float4*)&sB[r][c4 * 4] =
                *(const float4*)&g_Bt[(h0 + r) * N_TOK + j0 + c4 * 4];
        }
        __syncthreads();

        #pragma unroll 16
        for (int hk = 0; hk < 64; hk++) {
            float4 av = *(const float4*)&sA[hk][ty * 4];
            float4 bv = *(const float4*)&sB[hk][tx * 4];
            float a[4] = {av.x, av.y, av.z, av.w};
            float b[4] = {bv.x, bv.y, bv.z, bv.w};
            float wv = sw[h0 + hk];
            #pragma unroll
            for (int di = 0; di < 4; di++)
                #pragma unroll
                for (int dj = 0; dj < 4; dj++)
                    acc[di][dj] += wv * tanh_apx(a[di] + b[dj]);
        }
        __syncthreads();
    }

    const float ob = outBias[0];
    #pragma unroll
    for (int di = 0; di < 4; di++) {
        int row = i0 + ty * 4 + di;
        float4 o;
        o.x = acc[di][0] + ob;
        o.y = acc[di][1] + ob;
        o.z = acc[di][2] + ob;
        o.w = acc[di][3] + ob;
        *(float4*)&out[row * N_TOK + j0 + tx * 4] = o;
    }
}

// ---------------------------------------------------------------------------
extern "C" void kernel_launch(void* const* d_in, const int* in_sizes, int n_in,
                              void* d_out, int out_size)
{
    const float* lstms0   = (const float*)d_in[0];  // [1024, 256]
    const float* lstms1   = (const float*)d_in[1];  // [1024, 256]
    const float* W_foh    = (const float*)d_in[2];  // [512, 512]
    const float* W_fom    = (const float*)d_in[3];  // [512, 512]
    const float* catBias  = (const float*)d_in[4];  // [1, 1024]
    const float* hid2     = (const float*)d_in[5];  // [1024, 256]
    const float* hid2Bias = (const float*)d_in[6];  // [1, 256]
    const float* outLayer = (const float*)d_in[7];  // [256, 1]
    const float* outBias  = (const float*)d_in[8];  // [1, 1]
    float* out = (float*)d_out;                     // [1024, 1024]

    prep_kernel<<<512, 256>>>(lstms0, lstms1, W_foh, W_fom, hid2);
    p1_kernel<<<dim3(N_TOK / 64, HDIM / 64, 2), 256>>>(catBias);
    p2_kernel<<<dim3(N_TOK / 32, H2DIM / 64, 2), 128>>>(hid2Bias);
    pair_kernel<<<dim3(N_TOK / 64, N_TOK / 64), 256>>>(outLayer, outBias, out);
}

// round 13
// speedup vs baseline: 1.4595x; 1.0003x over previous
#include <cuda_runtime.h>

#define N_TOK 1024
#define LDIM  256
#define HDIM  512
#define H2DIM 256

// scratch (allocation-free rule: __device__ globals)
__device__ float g_xr[N_TOK * HDIM];          // concat(l0,l1), tf32-rounded
__device__ float g_wr[2 * HDIM * HDIM];       // W_foh | W_fom, tf32-rounded
__device__ float g_h2r[2 * HDIM * H2DIM];     // hid2, tf32-rounded
__device__ float g_ah[N_TOK * HDIM];          // tanh outputs, tf32-rounded
__device__ float g_am[N_TOK * HDIM];
__device__ float g_At[H2DIM * N_TOK];         // A + hid2Bias, transposed [h2][i]
__device__ float g_Bt[H2DIM * N_TOK];         // B, transposed [h2][j]

__device__ __forceinline__ float tanh_apx(float x) {
    float y;
    asm("tanh.approx.f32 %0, %1;" : "=f"(y) : "f"(x));
    return y;
}

__device__ __forceinline__ unsigned f2tf32(float x) {
    unsigned y;
    asm("cvt.rna.tf32.f32 %0, %1;" : "=r"(y) : "f"(x));
    return y;
}

__device__ __forceinline__ float rnd_tf32(float x) {
    return __uint_as_float(f2tf32(x));
}

__device__ __forceinline__ float4 rnd4(float4 v) {
    float4 r;
    r.x = rnd_tf32(v.x); r.y = rnd_tf32(v.y);
    r.z = rnd_tf32(v.z); r.w = rnd_tf32(v.w);
    return r;
}

// D += A(16x8) * B(8x8), tf32 inputs, fp32 accum
__device__ __forceinline__ void mma_tf32(float* d, const unsigned* a, const unsigned* b) {
    asm("mma.sync.aligned.m16n8k8.row.col.f32.tf32.tf32.f32 "
        "{%0,%1,%2,%3}, {%4,%5,%6,%7}, {%8,%9}, {%0,%1,%2,%3};"
        : "+f"(d[0]), "+f"(d[1]), "+f"(d[2]), "+f"(d[3])
        : "r"(a[0]), "r"(a[1]), "r"(a[2]), "r"(a[3]), "r"(b[0]), "r"(b[1]));
}

__device__ __forceinline__ void cp16(void* dst_smem, const void* src_gmem) {
    unsigned d = (unsigned)__cvta_generic_to_shared(dst_smem);
    asm volatile("cp.async.cg.shared.global [%0], [%1], 16;\n"
                 :: "r"(d), "l"(src_gmem));
}
#define CP_COMMIT()  asm volatile("cp.async.commit_group;\n" ::: "memory")
#define CP_WAIT(n)   asm volatile("cp.async.wait_group %0;\n" :: "n"(n) : "memory")

// ---------------------------------------------------------------------------
// Pre-pass: tf32-round X (concat), W_foh/W_fom, hid2 into device buffers.
// ---------------------------------------------------------------------------
__global__ __launch_bounds__(256) void prep_kernel(
    const float* __restrict__ l0, const float* __restrict__ l1,
    const float* __restrict__ Wfoh, const float* __restrict__ Wfom,
    const float* __restrict__ hid2)
{
    const int nt = gridDim.x * blockDim.x;
    const int t0 = blockIdx.x * blockDim.x + threadIdx.x;

    // X: 1024 rows x 128 float4 (first 64 from l0, next 64 from l1)
    for (int e = t0; e < N_TOK * 128; e += nt) {
        int i = e >> 7, c = e & 127;
        float4 v = (c < 64) ? ((const float4*)l0)[i * 64 + c]
                            : ((const float4*)l1)[i * 64 + (c - 64)];
        ((float4*)g_xr)[e] = rnd4(v);
    }
    // W: 2 x 65536 float4
    for (int e = t0; e < 2 * 65536; e += nt) {
        float4 v = (e < 65536) ? ((const float4*)Wfoh)[e]
                               : ((const float4*)Wfom)[e - 65536];
        ((float4*)g_wr)[e] = rnd4(v);
    }
    // hid2: 65536 float4
    for (int e = t0; e < 65536; e += nt) {
        ((float4*)g_h2r)[e] = rnd4(((const float4*)hid2)[e]);
    }
}

// ---------------------------------------------------------------------------
// P1 (tf32 MMA, 3-stage cp.async ring): ah/am = tanh(X@W + catBias), tf32-
// rounded on store. CTA 64x64, 256 thr (8 warps, 16x32 each), BK=32.
// Wait rule: group for chunk c must be retired before compute. For c<=NK-2
// one newer group (chunk c+1) may stay in flight -> CP_WAIT(1). At the final
// chunk there is NO newer group, so CP_WAIT(1) would leave chunk c itself
// pending -> must CP_WAIT(0). (This was the R11 correctness bug.)
// grid (16,8,2) = 256 CTAs.
// ---------------------------------------------------------------------------
__global__ __launch_bounds__(256) void p1_kernel(const float* __restrict__ catBias)
{
    const int z = blockIdx.z;
    const float* __restrict__ W = g_wr + z * HDIM * HDIM;
    float* __restrict__ out = z ? g_am : g_ah;
    const int m0 = blockIdx.x * 64;
    const int n0 = blockIdx.y * 64;
    const int tid = threadIdx.x;
    const int lane = tid & 31, warp = tid >> 5;
    const int wm = warp & 3;       // 4 m-chunks of 16
    const int wn = warp >> 2;      // 2 n-chunks of 32
    const int lr = lane >> 2;      // 0..7
    const int lc = lane & 3;       // 0..3

    __shared__ float Xs[3][64][36];   // [m][k]; LDS bank = lr*4+lc (bijective)
    __shared__ float Ws[3][32][72];   // [k][n]; LDS bank = lc*8+lr (bijective)

    const int xrow0 = tid >> 3, xc4 = (tid & 7) * 4;   // rows 0..31
    const int xrow1 = xrow0 + 32;                      // rows 32..63
    const int wkr0 = tid >> 4, wc4 = (tid & 15) * 4;   // k-rows 0..15
    const int wkr1 = wkr0 + 16;                        // k-rows 16..31

    const int NK = HDIM / 32;   // 16 chunks

    auto issue = [&](int buf, int k0) {
        cp16(&Xs[buf][xrow0][xc4], &g_xr[(m0 + xrow0) * HDIM + k0 + xc4]);
        cp16(&Xs[buf][xrow1][xc4], &g_xr[(m0 + xrow1) * HDIM + k0 + xc4]);
        cp16(&Ws[buf][wkr0][wc4], &W[(k0 + wkr0) * HDIM + n0 + wc4]);
        cp16(&Ws[buf][wkr1][wc4], &W[(k0 + wkr1) * HDIM + n0 + wc4]);
        CP_COMMIT();
    };

    float C[4][4] = {};

    issue(0, 0);
    issue(1, 32);
    for (int c = 0; c < NK; c++) {
        const int cur = c % 3;
        if (c + 1 < NK) { CP_WAIT(1); } else { CP_WAIT(0); }   // chunk c retired
        __syncthreads();
        if (c + 2 < NK) issue((c + 2) % 3, (c + 2) * 32);  // buf used at c-1: safe post-barrier

        #pragma unroll
        for (int ks = 0; ks < 32; ks += 8) {
            unsigned a[4], b[4][2];
            const int r = wm * 16 + lr;
            a[0] = __float_as_uint(Xs[cur][r][ks + lc]);
            a[1] = __float_as_uint(Xs[cur][r + 8][ks + lc]);
            a[2] = __float_as_uint(Xs[cur][r][ks + lc + 4]);
            a[3] = __float_as_uint(Xs[cur][r + 8][ks + lc + 4]);
            #pragma unroll
            for (int nt = 0; nt < 4; nt++) {
                int cn = wn * 32 + nt * 8 + lr;
                b[nt][0] = __float_as_uint(Ws[cur][ks + lc][cn]);
                b[nt][1] = __float_as_uint(Ws[cur][ks + lc + 4][cn]);
            }
            #pragma unroll
            for (int nt = 0; nt < 4; nt++)
                mma_tf32(C[nt], a, b[nt]);
        }
    }

    #pragma unroll
    for (int nt = 0; nt < 4; nt++) {
        int row = m0 + wm * 16 + lr;
        int col = n0 + wn * 32 + nt * 8 + 2 * lc;
        float cb0 = catBias[z * HDIM + col];
        float cb1 = catBias[z * HDIM + col + 1];
        out[row * HDIM + col]           = rnd_tf32(tanh_apx(C[nt][0] + cb0));
        out[row * HDIM + col + 1]       = rnd_tf32(tanh_apx(C[nt][1] + cb1));
        out[(row + 8) * HDIM + col]     = rnd_tf32(tanh_apx(C[nt][2] + cb0));
        out[(row + 8) * HDIM + col + 1] = rnd_tf32(tanh_apx(C[nt][3] + cb1));
    }
}

// ---------------------------------------------------------------------------
// P2 (tf32 MMA, 3-stage cp.async ring): At[h2][i] = ah@hid2[0:H] + bias (z=0)
//                                       Bt[h2][j] = am@hid2[H:2H]       (z=1)
// CTA 32x64, 128 thr (4 warps: 2x2, each 16x32), BK=32. grid (32,4,2)=256.
// Same final-chunk CP_WAIT(0) fix. Output TRANSPOSED fp32.
// ---------------------------------------------------------------------------
__global__ __launch_bounds__(128) void p2_kernel(const float* __restrict__ hid2Bias)
{
    const int z = blockIdx.z;
    const float* __restrict__ src = z ? g_am : g_ah;
    const float* __restrict__ W = g_h2r + z * HDIM * H2DIM;
    float* __restrict__ outp = z ? g_Bt : g_At;
    const int m0 = blockIdx.x * 32;
    const int n0 = blockIdx.y * 64;
    const int tid = threadIdx.x;
    const int lane = tid & 31, warp = tid >> 5;
    const int wm = warp & 1;       // 2 m-chunks of 16
    const int wn = warp >> 1;      // 2 n-chunks of 32
    const int lr = lane >> 2;
    const int lc = lane & 3;

    __shared__ float Xs[3][32][36];
    __shared__ float Ws[3][32][72];

    const int xrow0 = tid >> 3, xc4 = (tid & 7) * 4;   // rows 0..15
    const int xrow1 = xrow0 + 16;                      // rows 16..31
    const int wkr = tid >> 4, wc4 = (tid & 15) * 4;    // k-rows 0..7 (+8,+16,+24)

    const int NK = HDIM / 32;   // 16

    auto issue = [&](int buf, int k0) {
        cp16(&Xs[buf][xrow0][xc4], &src[(m0 + xrow0) * HDIM + k0 + xc4]);
        cp16(&Xs[buf][xrow1][xc4], &src[(m0 + xrow1) * HDIM + k0 + xc4]);
        #pragma unroll
        for (int q = 0; q < 4; q++)
            cp16(&Ws[buf][wkr + q * 8][wc4],
                 &W[(k0 + wkr + q * 8) * H2DIM + n0 + wc4]);
        CP_COMMIT();
    };

    float C[4][4] = {};

    issue(0, 0);
    issue(1, 32);
    for (int c = 0; c < NK; c++) {
        const int cur = c % 3;
        if (c + 1 < NK) { CP_WAIT(1); } else { CP_WAIT(0); }   // chunk c retired
        __syncthreads();
        if (c + 2 < NK) issue((c + 2) % 3, (c + 2) * 32);

        #pragma unroll
        for (int ks = 0; ks < 32; ks += 8) {
            unsigned a[4], b[4][2];
            const int r = wm * 16 + lr;
            a[0] = __float_as_uint(Xs[cur][r][ks + lc]);
            a[1] = __float_as_uint(Xs[cur][r + 8][ks + lc]);
            a[2] = __float_as_uint(Xs[cur][r][ks + lc + 4]);
            a[3] = __float_as_uint(Xs[cur][r + 8][ks + lc + 4]);
            #pragma unroll
            for (int nt = 0; nt < 4; nt++) {
                int cn = wn * 32 + nt * 8 + lr;
                b[nt][0] = __float_as_uint(Ws[cur][ks + lc][cn]);
                b[nt][1] = __float_as_uint(Ws[cur][ks + lc + 4][cn]);
            }
            #pragma unroll
            for (int nt = 0; nt < 4; nt++)
                mma_tf32(C[nt], a, b[nt]);
        }
    }

    #pragma unroll
    for (int nt = 0; nt < 4; nt++) {
        int row = m0 + wm * 16 + lr;               // token index
        int col = n0 + wn * 32 + nt * 8 + 2 * lc;  // h2 index
        float b0 = 0.f, b1 = 0.f;
        if (z == 0) { b0 = hid2Bias[col]; b1 = hid2Bias[col + 1]; }
        outp[col * N_TOK + row]           = C[nt][0] + b0;
        outp[(col + 1) * N_TOK + row]     = C[nt][1] + b1;
        outp[col * N_TOK + row + 8]       = C[nt][2] + b0;
        outp[(col + 1) * N_TOK + row + 8] = C[nt][3] + b1;
    }
}

// ---------------------------------------------------------------------------
// Main pairwise kernel: scores[i][j] = outBias + sum_h tanh(At[h][i]+Bt[h][j])*w[h]
// 64x64 CTA tile, 4x4 micro. grid 16x16 = 256 CTAs.
// launch_bounds(256,3): cap regs ~85 -> 24 warps/SM to keep MUFU fed.
// ---------------------------------------------------------------------------
__global__ __launch_bounds__(256, 3) void pair_kernel(
    const float* __restrict__ outLayer, const float* __restrict__ outBias,
    float* __restrict__ out)
{
    const int j0 = blockIdx.x * 64;
    const int i0 = blockIdx.y * 64;
    const int tid = threadIdx.x;
    const int tx = tid & 15, ty = tid >> 4;

    __shared__ float sA[64][64];
    __shared__ float sB[64][64];
    __shared__ float sw[H2DIM];

    sw[tid] = outLayer[tid];   // tid covers 0..255 == H2DIM

    float acc[4][4] = {};

    for (int h0 = 0; h0 < H2DIM; h0 += 64) {
        #pragma unroll
        for (int q = 0; q < 4; q++) {
            int e = q * 256 + tid;          // float4 units, 1024 total
            int r = e >> 4, c4 = e & 15;
            *(float4*)&sA[r][c4 * 4] =
                *(const float4*)&g_At[(h0 + r) * N_TOK + i0 + c4 * 4];
            *(float4*)&sB[r][c4 * 4] =
                *(const float4*)&g_Bt[(h0 + r) * N_TOK + j0 + c4 * 4];
        }
        __syncthreads();

        #pragma unroll 8
        for (int hk = 0; hk < 64; hk++) {
            float4 av = *(const float4*)&sA[hk][ty * 4];
            float4 bv = *(const float4*)&sB[hk][tx * 4];
            float a[4] = {av.x, av.y, av.z, av.w};
            float b[4] = {bv.x, bv.y, bv.z, bv.w};
            float wv = sw[h0 + hk];
            #pragma unroll
            for (int di = 0; di < 4; di++)
                #pragma unroll
                for (int dj = 0; dj < 4; dj++)
                    acc[di][dj] += wv * tanh_apx(a[di] + b[dj]);
        }
        __syncthreads();
    }

    const float ob = outBias[0];
    #pragma unroll
    for (int di = 0; di < 4; di++) {
        int row = i0 + ty * 4 + di;
        float4 o;
        o.x = acc[di][0] + ob;
        o.y = acc[di][1] + ob;
        o.z = acc[di][2] + ob;
        o.w = acc[di][3] + ob;
        *(float4*)&out[row * N_TOK + j0 + tx * 4] = o;
    }
}

// ---------------------------------------------------------------------------
extern "C" void kernel_launch(void* const* d_in, const int* in_sizes, int n_in,
                              void* d_out, int out_size)
{
    const float* lstms0   = (const float*)d_in[0];  // [1024, 256]
    const float* lstms1   = (const float*)d_in[1];  // [1024, 256]
    const float* W_foh    = (const float*)d_in[2];  // [512, 512]
    const float* W_fom    = (const float*)d_in[3];  // [512, 512]
    const float* catBias  = (const float*)d_in[4];  // [1, 1024]
    const float* hid2     = (const float*)d_in[5];  // [1024, 256]
    const float* hid2Bias = (const float*)d_in[6];  // [1, 256]
    const float* outLayer = (const float*)d_in[7];  // [256, 1]
    const float* outBias  = (const float*)d_in[8];  // [1, 1]
    float* out = (float*)d_out;                     // [1024, 1024]

    prep_kernel<<<512, 256>>>(lstms0, lstms1, W_foh, W_fom, hid2);
    p1_kernel<<<dim3(N_TOK / 64, HDIM / 64, 2), 256>>>(catBias);
    p2_kernel<<<dim3(N_TOK / 32, H2DIM / 64, 2), 128>>>(hid2Bias);
    pair_kernel<<<dim3(N_TOK / 64, N_TOK / 64), 256>>>(outLayer, outBias, out);
}